// round 3
// baseline (speedup 1.0000x reference)
#include <cuda_runtime.h>
#include <math.h>

// Problem dims
#define B_      8
#define T_      150
#define U_      40
#define EPROJS  512
#define DUNITS  1024
#define EMBED   512
#define JOINT_  640
#define ODIM    1024

// ---------------- device scratch (no allocation allowed) ----------------
__device__ float g_eys  [U_*B_*EMBED];          // (u*8+b, 512)
__device__ float g_X0   [U_*B_*4*DUNITS];       // precomputed input gates, (u*8+b, 4096)
__device__ float g_h0   [2*B_*DUNITS];          // ping-pong
__device__ float g_h1   [2*B_*DUNITS];
__device__ float g_c0   [B_*DUNITS];
__device__ float g_c1   [B_*DUNITS];
__device__ float g_hdec [B_*U_*DUNITS];         // (b*40+u, 1024)
__device__ float g_enc  [B_*T_*JOINT_];         // (b*150+t, 640)
__device__ float g_dec  [B_*U_*JOINT_];         // (b*40+u, 640)
__device__ float g_jnt  [B_*T_*U_*JOINT_];      // ((b*150+t)*40+u, 640)
__device__ float g_Wih0T[EMBED*4*DUNITS];       // [K][N] transposed weights
__device__ float g_WencT[EPROJS*JOINT_];
__device__ float g_WdecT[DUNITS*JOINT_];
__device__ float g_WoutT[JOINT_*ODIM];

// ---------------- f32x2 helpers (FFMA2: PTX-only, 2x fp32 throughput) ----------------
__device__ __forceinline__ unsigned long long pk2(float lo, float hi) {
    unsigned long long r;
    asm("mov.b64 %0, {%1, %2};" : "=l"(r) : "f"(lo), "f"(hi));
    return r;
}
__device__ __forceinline__ unsigned long long fma2(unsigned long long a,
                                                   unsigned long long b,
                                                   unsigned long long c) {
    unsigned long long d;
    asm("fma.rn.f32x2 %0, %1, %2, %3;" : "=l"(d) : "l"(a), "l"(b), "l"(c));
    return d;
}
__device__ __forceinline__ float2 upk2(unsigned long long v) {
    float2 r;
    asm("mov.b64 {%0, %1}, %2;" : "=f"(r.x), "=f"(r.y) : "l"(v));
    return r;
}

__device__ __forceinline__ float sigmf(float x) { return 1.0f / (1.0f + __expf(-x)); }

// ---------------- transpose: Wt[k][n] = W[n][k] ----------------
__global__ void transpose_kernel(const float* __restrict__ W, float* __restrict__ Wt,
                                 int N, int K) {
    __shared__ float t[32][33];
    int kb = blockIdx.x * 32, nb = blockIdx.y * 32;
    int x = threadIdx.x, y = threadIdx.y;
    #pragma unroll
    for (int yy = y; yy < 32; yy += 8) {
        int n = nb + yy, k = kb + x;
        if (n < N && k < K) t[yy][x] = W[(size_t)n * K + k];
    }
    __syncthreads();
    #pragma unroll
    for (int yy = y; yy < 32; yy += 8) {
        int k = kb + yy, n = nb + x;
        if (k < K && n < N) Wt[(size_t)k * N + n] = t[x][yy];
    }
}

// ---------------- embedding gather: g_eys[u*8+b] = embW[ys[b][u]] ----------------
__global__ void embed_kernel(const int* __restrict__ ys, const float* __restrict__ embW) {
    int row = blockIdx.x;            // = u*8 + b
    int u = row >> 3, b = row & 7;
    int tok = ys[b * U_ + u];
    const float4* src = (const float4*)(embW + (size_t)tok * EMBED);
    float4* dst = (float4*)(g_eys + (size_t)row * EMBED);
    for (int i = threadIdx.x; i < EMBED / 4; i += blockDim.x) dst[i] = src[i];
}

__global__ void init_state_kernel() {
    int i = blockIdx.x * blockDim.x + threadIdx.x;
    if (i < 2 * B_ * DUNITS) { g_h0[i] = 0.f; g_h1[i] = 0.f; }
    if (i < B_ * DUNITS)     { g_c0[i] = 0.f; g_c1[i] = 0.f; }
}

// ---------------- generic fp32 GEMM via FFMA2 ----------------
// C[M][N] = A[M][K] @ Wt (Wt is [K][N]) + bias1 (+ bias2)
// Requires N % 128 == 0, K % 16 == 0. M predicated.
__global__ __launch_bounds__(256, 2)
void gemm_f32x2(const float* __restrict__ A, const float* __restrict__ Wt,
                const float* __restrict__ bias1, const float* __restrict__ bias2,
                float* __restrict__ C, int M, int N, int K) {
    __shared__ float As[128][16];   // [m][k]
    __shared__ float Bs[16][128];   // [k][n]
    const int tid = threadIdx.x;
    const int m0 = blockIdx.y * 128;
    const int n0 = blockIdx.x * 128;
    const int tr = tid >> 4;          // 0..15 (m micro-tile)
    const int tc = tid & 15;          // 0..15 (n micro-tile)
    const int lr = tid >> 2;          // 0..63 A-load row
    const int lk = (tid & 3) << 2;    // A-load k offset
    const int kr = tid >> 5;          // 0..7  B-load k row
    const int kc = (tid & 31) << 2;   // B-load n offset

    unsigned long long acc[8][4];
    #pragma unroll
    for (int i = 0; i < 8; i++)
        #pragma unroll
        for (int p = 0; p < 4; p++) acc[i][p] = 0ull;

    for (int kt = 0; kt < K; kt += 16) {
        #pragma unroll
        for (int h = 0; h < 2; h++) {
            int m = lr + h * 64;
            int gm = m0 + m;
            float4 v = make_float4(0.f, 0.f, 0.f, 0.f);
            if (gm < M) v = *(const float4*)(A + (size_t)gm * K + kt + lk);
            *(float4*)(&As[m][lk]) = v;
            int k = kr + h * 8;
            float4 w = *(const float4*)(Wt + (size_t)(kt + k) * N + n0 + kc);
            *(float4*)(&Bs[k][kc]) = w;
        }
        __syncthreads();
        const float* ap = &As[tr * 8][0];
        const float4* bp = (const float4*)&Bs[0][tc * 8];
        #pragma unroll
        for (int k = 0; k < 16; k++) {
            float4 bv0 = bp[k * 32];
            float4 bv1 = bp[k * 32 + 1];
            unsigned long long bpk[4];
            bpk[0] = pk2(bv0.x, bv0.y);
            bpk[1] = pk2(bv0.z, bv0.w);
            bpk[2] = pk2(bv1.x, bv1.y);
            bpk[3] = pk2(bv1.z, bv1.w);
            #pragma unroll
            for (int i = 0; i < 8; i++) {
                float a = ap[i * 16 + k];
                unsigned long long a2 = pk2(a, a);
                #pragma unroll
                for (int p = 0; p < 4; p++) acc[i][p] = fma2(a2, bpk[p], acc[i][p]);
            }
        }
        __syncthreads();
    }
    float bias[8];
    #pragma unroll
    for (int i = 0; i < 8; i++) {
        int n = n0 + tc * 8 + i;
        float bb = bias1[n];
        if (bias2) bb += bias2[n];
        bias[i] = bb;
    }
    #pragma unroll
    for (int i = 0; i < 8; i++) {
        int gm = m0 + tr * 8 + i;
        if (gm < M) {
            float2 v0 = upk2(acc[i][0]);
            float2 v1 = upk2(acc[i][1]);
            float2 v2 = upk2(acc[i][2]);
            float2 v3 = upk2(acc[i][3]);
            float4 o0 = make_float4(v0.x + bias[0], v0.y + bias[1], v1.x + bias[2], v1.y + bias[3]);
            float4 o1 = make_float4(v2.x + bias[4], v2.y + bias[5], v3.x + bias[6], v3.y + bias[7]);
            float* cp = C + (size_t)gm * N + n0 + tc * 8;
            *(float4*)cp = o0;
            *(float4*)(cp + 4) = o1;
        }
    }
}

// ---------------- LSTM recurrent kernels ----------------
// One warp handles gate column j for all 4 gates x 8 batches.
__device__ __forceinline__ void lstm_load_h(float* hs, const float* __restrict__ src, int tid) {
    const float4* s = (const float4*)src;
    float4* d = (float4*)hs;
    #pragma unroll
    for (int i = 0; i < 8; i++) d[tid + 256 * i] = s[tid + 256 * i];
}

__device__ __forceinline__ void lstm_accum(float acc[4][8], const float* __restrict__ W,
                                           const float4* hs4, int j, int lane) {
    const float4* W4 = (const float4*)W;
    #pragma unroll 2
    for (int k0 = 0; k0 < 256; k0 += 32) {
        float4 w[4];
        #pragma unroll
        for (int r = 0; r < 4; r++)
            w[r] = __ldg(&W4[(size_t)(r * DUNITS + j) * 256 + k0 + lane]);
        #pragma unroll
        for (int b = 0; b < 8; b++) {
            float4 hv = hs4[b * 256 + k0 + lane];
            #pragma unroll
            for (int r = 0; r < 4; r++)
                acc[r][b] += w[r].x * hv.x + w[r].y * hv.y + w[r].z * hv.z + w[r].w * hv.w;
        }
    }
}

__device__ __forceinline__ void lstm_reduce(float acc[4][8]) {
    #pragma unroll
    for (int r = 0; r < 4; r++)
        #pragma unroll
        for (int b = 0; b < 8; b++)
            #pragma unroll
            for (int off = 16; off; off >>= 1)
                acc[r][b] += __shfl_xor_sync(0xffffffffu, acc[r][b], off);
}

__global__ __launch_bounds__(256)
void lstm_cell0(const float* __restrict__ Whh, const float* __restrict__ hprev,
                float* __restrict__ hcur, int u) {
    __shared__ float hs[B_ * DUNITS];
    int tid = threadIdx.x, lane = tid & 31, warp = tid >> 5;
    int j = blockIdx.x * 8 + warp;
    lstm_load_h(hs, hprev, tid);
    __syncthreads();
    float acc[4][8];
    #pragma unroll
    for (int r = 0; r < 4; r++)
        #pragma unroll
        for (int b = 0; b < 8; b++) acc[r][b] = 0.f;
    lstm_accum(acc, Whh, (const float4*)hs, j, lane);
    lstm_reduce(acc);
    if (lane < 8) {
        int b = lane;
        const float* x0 = &g_X0[(size_t)(u * 8 + b) * 4 * DUNITS];
        float gi = acc[0][b] + x0[j];
        float gf = acc[1][b] + x0[DUNITS + j];
        float gg = acc[2][b] + x0[2 * DUNITS + j];
        float go = acc[3][b] + x0[3 * DUNITS + j];
        float c = g_c0[b * DUNITS + j];
        float cn = sigmf(gf) * c + sigmf(gi) * tanhf(gg);
        float hn = sigmf(go) * tanhf(cn);
        g_c0[b * DUNITS + j] = cn;
        hcur[b * DUNITS + j] = hn;
    }
}

__global__ __launch_bounds__(256)
void lstm_cell1(const float* __restrict__ Wih, const float* __restrict__ Whh,
                const float* __restrict__ bih, const float* __restrict__ bhh,
                const float* __restrict__ h0cur, const float* __restrict__ h1prev,
                float* __restrict__ h1cur, int u) {
    __shared__ float hs[B_ * DUNITS];
    int tid = threadIdx.x, lane = tid & 31, warp = tid >> 5;
    int j = blockIdx.x * 8 + warp;
    float acc[4][8];
    #pragma unroll
    for (int r = 0; r < 4; r++)
        #pragma unroll
        for (int b = 0; b < 8; b++) acc[r][b] = 0.f;
    lstm_load_h(hs, h0cur, tid);
    __syncthreads();
    lstm_accum(acc, Wih, (const float4*)hs, j, lane);
    __syncthreads();
    lstm_load_h(hs, h1prev, tid);
    __syncthreads();
    lstm_accum(acc, Whh, (const float4*)hs, j, lane);
    lstm_reduce(acc);
    if (lane < 8) {
        int b = lane;
        float gi = acc[0][b] + bih[j] + bhh[j];
        float gf = acc[1][b] + bih[DUNITS + j] + bhh[DUNITS + j];
        float gg = acc[2][b] + bih[2 * DUNITS + j] + bhh[2 * DUNITS + j];
        float go = acc[3][b] + bih[3 * DUNITS + j] + bhh[3 * DUNITS + j];
        float c = g_c1[b * DUNITS + j];
        float cn = sigmf(gf) * c + sigmf(gi) * tanhf(gg);
        float hn = sigmf(go) * tanhf(cn);
        g_c1[b * DUNITS + j] = cn;
        h1cur[b * DUNITS + j] = hn;
        g_hdec[(size_t)(b * U_ + u) * DUNITS + j] = hn;
    }
}

// ---------------- joint tanh materialization ----------------
// g_jnt[row][j] = tanh(g_enc[bt][j] + g_dec[b*40+u][j]), row = bt*40+u
__global__ void tanh_joint_kernel() {
    int idx = blockIdx.x * blockDim.x + threadIdx.x;   // float4 index
    const int TOTAL4 = B_ * T_ * U_ * (JOINT_ / 4);    // 7,680,000
    if (idx >= TOTAL4) return;
    int row = idx / (JOINT_ / 4);
    int j4 = idx - row * (JOINT_ / 4);
    int u = row % U_;
    int bt = row / U_;
    int b = bt / T_;
    float4 e = *(const float4*)&g_enc[(size_t)bt * JOINT_ + j4 * 4];
    float4 d = *(const float4*)&g_dec[(size_t)(b * U_ + u) * JOINT_ + j4 * 4];
    float4 o;
    o.x = tanhf(e.x + d.x);
    o.y = tanhf(e.y + d.y);
    o.z = tanhf(e.z + d.z);
    o.w = tanhf(e.w + d.w);
    *(float4*)&g_jnt[(size_t)idx * 4] = o;
}

// ---------------- launcher ----------------
extern "C" void kernel_launch(void* const* d_in, const int* in_sizes, int n_in,
                              void* d_out, int out_size) {
    const float* hs_pad = (const float*)d_in[0];
    const int*   ys     = (const int*)  d_in[1];
    const float* embW   = (const float*)d_in[2];
    const float* W_ih0  = (const float*)d_in[3];
    const float* W_hh0  = (const float*)d_in[4];
    const float* b_ih0  = (const float*)d_in[5];
    const float* b_hh0  = (const float*)d_in[6];
    const float* W_ih1  = (const float*)d_in[7];
    const float* W_hh1  = (const float*)d_in[8];
    const float* b_ih1  = (const float*)d_in[9];
    const float* b_hh1  = (const float*)d_in[10];
    const float* W_enc  = (const float*)d_in[11];
    const float* b_enc  = (const float*)d_in[12];
    const float* W_dec  = (const float*)d_in[13];
    const float* b_dec  = (const float*)d_in[14];
    const float* W_out  = (const float*)d_in[15];
    const float* b_out  = (const float*)d_in[16];
    float* out = (float*)d_out;

    float *p_eys, *p_X0, *p_h0, *p_h1, *p_hdec, *p_enc, *p_dec, *p_jnt;
    float *p_Wih0T, *p_WencT, *p_WdecT, *p_WoutT;
    cudaGetSymbolAddress((void**)&p_eys, g_eys);
    cudaGetSymbolAddress((void**)&p_X0, g_X0);
    cudaGetSymbolAddress((void**)&p_h0, g_h0);
    cudaGetSymbolAddress((void**)&p_h1, g_h1);
    cudaGetSymbolAddress((void**)&p_hdec, g_hdec);
    cudaGetSymbolAddress((void**)&p_enc, g_enc);
    cudaGetSymbolAddress((void**)&p_dec, g_dec);
    cudaGetSymbolAddress((void**)&p_jnt, g_jnt);
    cudaGetSymbolAddress((void**)&p_Wih0T, g_Wih0T);
    cudaGetSymbolAddress((void**)&p_WencT, g_WencT);
    cudaGetSymbolAddress((void**)&p_WdecT, g_WdecT);
    cudaGetSymbolAddress((void**)&p_WoutT, g_WoutT);

    dim3 tb(32, 8);
    transpose_kernel<<<dim3(EMBED / 32, 4 * DUNITS / 32), tb>>>(W_ih0, p_Wih0T, 4 * DUNITS, EMBED);
    transpose_kernel<<<dim3(EPROJS / 32, JOINT_ / 32), tb>>>(W_enc, p_WencT, JOINT_, EPROJS);
    transpose_kernel<<<dim3(DUNITS / 32, JOINT_ / 32), tb>>>(W_dec, p_WdecT, JOINT_, DUNITS);
    transpose_kernel<<<dim3(JOINT_ / 32, ODIM / 32), tb>>>(W_out, p_WoutT, ODIM, JOINT_);

    embed_kernel<<<U_ * B_, 128>>>(ys, embW);
    init_state_kernel<<<64, 256>>>();

    // X0 = eys @ W_ih0^T + b_ih0 + b_hh0   (rows = u*8+b)
    gemm_f32x2<<<dim3(4 * DUNITS / 128, (U_ * B_ + 127) / 128), 256>>>(
        p_eys, p_Wih0T, b_ih0, b_hh0, p_X0, U_ * B_, 4 * DUNITS, EMBED);

    for (int u = 0; u < U_; u++) {
        int cur = u & 1, prev = cur ^ 1;
        lstm_cell0<<<128, 256>>>(W_hh0, p_h0 + prev * B_ * DUNITS, p_h0 + cur * B_ * DUNITS, u);
        lstm_cell1<<<128, 256>>>(W_ih1, W_hh1, b_ih1, b_hh1,
                                 p_h0 + cur * B_ * DUNITS,
                                 p_h1 + prev * B_ * DUNITS,
                                 p_h1 + cur * B_ * DUNITS, u);
    }

    // enc_proj = hs_pad @ W_enc^T + b_enc  (rows = b*150+t)
    gemm_f32x2<<<dim3(JOINT_ / 128, (B_ * T_ + 127) / 128), 256>>>(
        hs_pad, p_WencT, b_enc, nullptr, p_enc, B_ * T_, JOINT_, EPROJS);
    // dec_proj = h_dec @ W_dec^T + b_dec   (rows = b*40+u)
    gemm_f32x2<<<dim3(JOINT_ / 128, (B_ * U_ + 127) / 128), 256>>>(
        p_hdec, p_WdecT, b_dec, nullptr, p_dec, B_ * U_, JOINT_, DUNITS);

    tanh_joint_kernel<<<(B_ * T_ * U_ * (JOINT_ / 4) + 255) / 256, 256>>>();

    // out = jnt @ W_out^T + b_out  (rows = (b*150+t)*40+u, exactly the output layout)
    gemm_f32x2<<<dim3(ODIM / 128, (B_ * T_ * U_ + 127) / 128), 256>>>(
        p_jnt, p_WoutT, b_out, nullptr, out, B_ * T_ * U_, ODIM, JOINT_);
}

// round 6
// speedup vs baseline: 1.6128x; 1.6128x over previous
#include <cuda_runtime.h>
#include <cuda_bf16.h>
#include <math.h>
#include <stdint.h>

// Problem dims
#define B_      8
#define T_      150
#define U_      40
#define EPROJS  512
#define DUNITS  1024
#define EMBED   512
#define JOINT_  640
#define ODIM    1024

#define MROWS   (B_*T_*U_)     // 48000

// ---------------- device scratch (no allocation allowed) ----------------
__device__ float g_eys  [U_*B_*EMBED];
__device__ float g_X0   [U_*B_*4*DUNITS];
__device__ float g_h0   [2*B_*DUNITS];
__device__ float g_h1   [2*B_*DUNITS];
__device__ float g_c0   [B_*DUNITS];
__device__ float g_c1   [B_*DUNITS];
__device__ float g_hdec [B_*U_*DUNITS];
__device__ float g_enc  [B_*T_*JOINT_];
__device__ float g_dec  [B_*U_*JOINT_];
__device__ float g_Wih0T[EMBED*4*DUNITS];
__device__ float g_WencT[EPROJS*JOINT_];
__device__ float g_WdecT[DUNITS*JOINT_];
// split-bf16 operands for the tensor-core joint GEMM (16B-aligned for uint4/cp.async)
__device__ __align__(16) __nv_bfloat16 g_jntH[MROWS*JOINT_];
__device__ __align__(16) __nv_bfloat16 g_jntL[MROWS*JOINT_];
__device__ __align__(16) __nv_bfloat16 g_WoutH[ODIM*JOINT_];
__device__ __align__(16) __nv_bfloat16 g_WoutL[ODIM*JOINT_];

// ---------------- f32x2 helpers ----------------
__device__ __forceinline__ unsigned long long pk2(float lo, float hi) {
    unsigned long long r;
    asm("mov.b64 %0, {%1, %2};" : "=l"(r) : "f"(lo), "f"(hi));
    return r;
}
__device__ __forceinline__ unsigned long long fma2(unsigned long long a,
                                                   unsigned long long b,
                                                   unsigned long long c) {
    unsigned long long d;
    asm("fma.rn.f32x2 %0, %1, %2, %3;" : "=l"(d) : "l"(a), "l"(b), "l"(c));
    return d;
}
__device__ __forceinline__ float2 upk2(unsigned long long v) {
    float2 r;
    asm("mov.b64 {%0, %1}, %2;" : "=f"(r.x), "=f"(r.y) : "l"(v));
    return r;
}
__device__ __forceinline__ float sigmf(float x) { return 1.0f / (1.0f + __expf(-x)); }

// ---------------- misc helpers ----------------
__device__ __forceinline__ uint32_t smem_u32(const void* p) {
    uint32_t a;
    asm("{ .reg .u64 t; cvta.to.shared.u64 t, %1; cvt.u32.u64 %0, t; }" : "=r"(a) : "l"(p));
    return a;
}
#define SW128(off) ((off) ^ (((off) >> 3) & 0x70))

__device__ __forceinline__ void cp_async16(uint32_t dst, const void* src) {
    asm volatile("cp.async.cg.shared.global [%0], [%1], 16;" :: "r"(dst), "l"(src));
}
__device__ __forceinline__ void cp_commit() { asm volatile("cp.async.commit_group;" ::: "memory"); }
template<int N> __device__ __forceinline__ void cp_wait() {
    asm volatile("cp.async.wait_group %0;" :: "n"(N) : "memory");
}
__device__ __forceinline__ void ldmx4(uint32_t* r, uint32_t addr) {
    asm volatile("ldmatrix.sync.aligned.m8n8.x4.shared.b16 {%0,%1,%2,%3}, [%4];"
                 : "=r"(r[0]), "=r"(r[1]), "=r"(r[2]), "=r"(r[3]) : "r"(addr));
}
__device__ __forceinline__ void mma16816(float* c, const uint32_t* a, const uint32_t* b) {
    asm volatile(
        "mma.sync.aligned.m16n8k16.row.col.f32.bf16.bf16.f32 "
        "{%0,%1,%2,%3}, {%4,%5,%6,%7}, {%8,%9}, {%0,%1,%2,%3};"
        : "+f"(c[0]), "+f"(c[1]), "+f"(c[2]), "+f"(c[3])
        : "r"(a[0]), "r"(a[1]), "r"(a[2]), "r"(a[3]), "r"(b[0]), "r"(b[1]));
}

// ---------------- transpose ----------------
__global__ void transpose_kernel(const float* __restrict__ W, float* __restrict__ Wt,
                                 int N, int K) {
    __shared__ float t[32][33];
    int kb = blockIdx.x * 32, nb = blockIdx.y * 32;
    int x = threadIdx.x, y = threadIdx.y;
    #pragma unroll
    for (int yy = y; yy < 32; yy += 8) {
        int n = nb + yy, k = kb + x;
        if (n < N && k < K) t[yy][x] = W[(size_t)n * K + k];
    }
    __syncthreads();
    #pragma unroll
    for (int yy = y; yy < 32; yy += 8) {
        int k = kb + yy, n = nb + x;
        if (k < K && n < N) Wt[(size_t)k * N + n] = t[x][yy];
    }
}

// ---------------- embedding gather ----------------
__global__ void embed_kernel(const int* __restrict__ ys, const float* __restrict__ embW) {
    int row = blockIdx.x;            // u*8 + b
    int u = row >> 3, b = row & 7;
    int tok = ys[b * U_ + u];
    const float4* src = (const float4*)(embW + (size_t)tok * EMBED);
    float4* dst = (float4*)(g_eys + (size_t)row * EMBED);
    for (int i = threadIdx.x; i < EMBED / 4; i += blockDim.x) dst[i] = src[i];
}

__global__ void init_state_kernel() {
    int i = blockIdx.x * blockDim.x + threadIdx.x;
    if (i < 2 * B_ * DUNITS) { g_h0[i] = 0.f; g_h1[i] = 0.f; }
    if (i < B_ * DUNITS)     { g_c0[i] = 0.f; g_c1[i] = 0.f; }
}

// ---------------- split W_out to bf16 hi/lo ----------------
__global__ void split_wout_kernel(const float* __restrict__ W) {
    int i = blockIdx.x * blockDim.x + threadIdx.x;
    if (i < ODIM * JOINT_) {
        float w = W[i];
        __nv_bfloat16 h = __float2bfloat16(w);
        g_WoutH[i] = h;
        g_WoutL[i] = __float2bfloat16(w - __bfloat162float(h));
    }
}

// ---------------- fp32 GEMM via FFMA2 (small GEMMs) ----------------
__global__ __launch_bounds__(256, 2)
void gemm_f32x2(const float* __restrict__ A, const float* __restrict__ Wt,
                const float* __restrict__ bias1, const float* __restrict__ bias2,
                float* __restrict__ C, int M, int N, int K) {
    __shared__ float As[128][16];
    __shared__ float Bs[16][128];
    const int tid = threadIdx.x;
    const int m0 = blockIdx.y * 128;
    const int n0 = blockIdx.x * 128;
    const int tr = tid >> 4;
    const int tc = tid & 15;
    const int lr = tid >> 2;
    const int lk = (tid & 3) << 2;
    const int kr = tid >> 5;
    const int kc = (tid & 31) << 2;

    unsigned long long acc[8][4];
    #pragma unroll
    for (int i = 0; i < 8; i++)
        #pragma unroll
        for (int p = 0; p < 4; p++) acc[i][p] = 0ull;

    for (int kt = 0; kt < K; kt += 16) {
        #pragma unroll
        for (int h = 0; h < 2; h++) {
            int m = lr + h * 64;
            int gm = m0 + m;
            float4 v = make_float4(0.f, 0.f, 0.f, 0.f);
            if (gm < M) v = *(const float4*)(A + (size_t)gm * K + kt + lk);
            *(float4*)(&As[m][lk]) = v;
            int k = kr + h * 8;
            float4 w = *(const float4*)(Wt + (size_t)(kt + k) * N + n0 + kc);
            *(float4*)(&Bs[k][kc]) = w;
        }
        __syncthreads();
        const float* ap = &As[tr * 8][0];
        const float4* bp = (const float4*)&Bs[0][tc * 8];
        #pragma unroll
        for (int k = 0; k < 16; k++) {
            float4 bv0 = bp[k * 32];
            float4 bv1 = bp[k * 32 + 1];
            unsigned long long bpk[4];
            bpk[0] = pk2(bv0.x, bv0.y);
            bpk[1] = pk2(bv0.z, bv0.w);
            bpk[2] = pk2(bv1.x, bv1.y);
            bpk[3] = pk2(bv1.z, bv1.w);
            #pragma unroll
            for (int i = 0; i < 8; i++) {
                float a = ap[i * 16 + k];
                unsigned long long a2 = pk2(a, a);
                #pragma unroll
                for (int p = 0; p < 4; p++) acc[i][p] = fma2(a2, bpk[p], acc[i][p]);
            }
        }
        __syncthreads();
    }
    float bias[8];
    #pragma unroll
    for (int i = 0; i < 8; i++) {
        int n = n0 + tc * 8 + i;
        float bb = bias1[n];
        if (bias2) bb += bias2[n];
        bias[i] = bb;
    }
    #pragma unroll
    for (int i = 0; i < 8; i++) {
        int gm = m0 + tr * 8 + i;
        if (gm < M) {
            float2 v0 = upk2(acc[i][0]);
            float2 v1 = upk2(acc[i][1]);
            float2 v2 = upk2(acc[i][2]);
            float2 v3 = upk2(acc[i][3]);
            float4 o0 = make_float4(v0.x + bias[0], v0.y + bias[1], v1.x + bias[2], v1.y + bias[3]);
            float4 o1 = make_float4(v2.x + bias[4], v2.y + bias[5], v3.x + bias[6], v3.y + bias[7]);
            float* cp = C + (size_t)gm * N + n0 + tc * 8;
            *(float4*)cp = o0;
            *(float4*)(cp + 4) = o1;
        }
    }
}

// ---------------- LSTM recurrent kernels ----------------
__device__ __forceinline__ void lstm_load_h(float* hs, const float* __restrict__ src, int tid) {
    const float4* s = (const float4*)src;
    float4* d = (float4*)hs;
    #pragma unroll
    for (int i = 0; i < 8; i++) d[tid + 256 * i] = s[tid + 256 * i];
}

__device__ __forceinline__ void lstm_accum(float acc[4][8], const float* __restrict__ W,
                                           const float4* hs4, int j, int lane) {
    const float4* W4 = (const float4*)W;
    #pragma unroll 2
    for (int k0 = 0; k0 < 256; k0 += 32) {
        float4 w[4];
        #pragma unroll
        for (int r = 0; r < 4; r++)
            w[r] = __ldg(&W4[(size_t)(r * DUNITS + j) * 256 + k0 + lane]);
        #pragma unroll
        for (int b = 0; b < 8; b++) {
            float4 hv = hs4[b * 256 + k0 + lane];
            #pragma unroll
            for (int r = 0; r < 4; r++)
                acc[r][b] += w[r].x * hv.x + w[r].y * hv.y + w[r].z * hv.z + w[r].w * hv.w;
        }
    }
}

__device__ __forceinline__ void lstm_reduce(float acc[4][8]) {
    #pragma unroll
    for (int r = 0; r < 4; r++)
        #pragma unroll
        for (int b = 0; b < 8; b++)
            #pragma unroll
            for (int off = 16; off; off >>= 1)
                acc[r][b] += __shfl_xor_sync(0xffffffffu, acc[r][b], off);
}

__global__ __launch_bounds__(256)
void lstm_cell0(const float* __restrict__ Whh, const float* __restrict__ hprev,
                float* __restrict__ hcur, int u) {
    __shared__ float hs[B_ * DUNITS];
    int tid = threadIdx.x, lane = tid & 31, warp = tid >> 5;
    int j = blockIdx.x * 8 + warp;
    lstm_load_h(hs, hprev, tid);
    __syncthreads();
    float acc[4][8];
    #pragma unroll
    for (int r = 0; r < 4; r++)
        #pragma unroll
        for (int b = 0; b < 8; b++) acc[r][b] = 0.f;
    lstm_accum(acc, Whh, (const float4*)hs, j, lane);
    lstm_reduce(acc);
    if (lane < 8) {
        int b = lane;
        const float* x0 = &g_X0[(size_t)(u * 8 + b) * 4 * DUNITS];
        float gi = acc[0][b] + x0[j];
        float gf = acc[1][b] + x0[DUNITS + j];
        float gg = acc[2][b] + x0[2 * DUNITS + j];
        float go = acc[3][b] + x0[3 * DUNITS + j];
        float c = g_c0[b * DUNITS + j];
        float cn = sigmf(gf) * c + sigmf(gi) * tanhf(gg);
        float hn = sigmf(go) * tanhf(cn);
        g_c0[b * DUNITS + j] = cn;
        hcur[b * DUNITS + j] = hn;
    }
}

__global__ __launch_bounds__(256)
void lstm_cell1(const float* __restrict__ Wih, const float* __restrict__ Whh,
                const float* __restrict__ bih, const float* __restrict__ bhh,
                const float* __restrict__ h0cur, const float* __restrict__ h1prev,
                float* __restrict__ h1cur, int u) {
    __shared__ float hs[B_ * DUNITS];
    int tid = threadIdx.x, lane = tid & 31, warp = tid >> 5;
    int j = blockIdx.x * 8 + warp;
    float acc[4][8];
    #pragma unroll
    for (int r = 0; r < 4; r++)
        #pragma unroll
        for (int b = 0; b < 8; b++) acc[r][b] = 0.f;
    lstm_load_h(hs, h0cur, tid);
    __syncthreads();
    lstm_accum(acc, Wih, (const float4*)hs, j, lane);
    __syncthreads();
    lstm_load_h(hs, h1prev, tid);
    __syncthreads();
    lstm_accum(acc, Whh, (const float4*)hs, j, lane);
    lstm_reduce(acc);
    if (lane < 8) {
        int b = lane;
        float gi = acc[0][b] + bih[j] + bhh[j];
        float gf = acc[1][b] + bih[DUNITS + j] + bhh[DUNITS + j];
        float gg = acc[2][b] + bih[2 * DUNITS + j] + bhh[2 * DUNITS + j];
        float go = acc[3][b] + bih[3 * DUNITS + j] + bhh[3 * DUNITS + j];
        float c = g_c1[b * DUNITS + j];
        float cn = sigmf(gf) * c + sigmf(gi) * tanhf(gg);
        float hn = sigmf(go) * tanhf(cn);
        g_c1[b * DUNITS + j] = cn;
        h1cur[b * DUNITS + j] = hn;
        g_hdec[(size_t)(b * U_ + u) * DUNITS + j] = hn;
    }
}

// ---------------- joint tanh + split to bf16 hi/lo ----------------
__global__ void tanh_split_kernel() {
    int idx = blockIdx.x * blockDim.x + threadIdx.x;     // per 8 elements
    const int TOT8 = MROWS * (JOINT_ / 8);               // 3,840,000
    if (idx >= TOT8) return;
    int row = idx / (JOINT_ / 8);
    int j8 = idx - row * (JOINT_ / 8);
    int u = row % U_;
    int bt = row / U_;
    int b = bt / T_;
    const float4* e4 = (const float4*)&g_enc[(size_t)bt * JOINT_ + j8 * 8];
    const float4* d4 = (const float4*)&g_dec[(size_t)(b * U_ + u) * JOINT_ + j8 * 8];
    float t[8];
    #pragma unroll
    for (int q = 0; q < 2; q++) {
        float4 e = e4[q], d = d4[q];
        t[q * 4 + 0] = tanhf(e.x + d.x);
        t[q * 4 + 1] = tanhf(e.y + d.y);
        t[q * 4 + 2] = tanhf(e.z + d.z);
        t[q * 4 + 3] = tanhf(e.w + d.w);
    }
    uint4 hv, lv;
    __nv_bfloat162* hp = (__nv_bfloat162*)&hv;
    __nv_bfloat162* lp = (__nv_bfloat162*)&lv;
    #pragma unroll
    for (int q = 0; q < 4; q++) {
        __nv_bfloat16 h0 = __float2bfloat16(t[q * 2 + 0]);
        __nv_bfloat16 h1 = __float2bfloat16(t[q * 2 + 1]);
        __nv_bfloat16 l0 = __float2bfloat16(t[q * 2 + 0] - __bfloat162float(h0));
        __nv_bfloat16 l1 = __float2bfloat16(t[q * 2 + 1] - __bfloat162float(h1));
        hp[q] = __halves2bfloat162(h0, h1);
        lp[q] = __halves2bfloat162(l0, l1);
    }
    *(uint4*)&g_jntH[(size_t)row * JOINT_ + j8 * 8] = hv;
    *(uint4*)&g_jntL[(size_t)row * JOINT_ + j8 * 8] = lv;
}

// ---------------- joint GEMM via mma.sync (split bf16, fp32 accum) ----------------
// C[48000][1024] = tanh_jnt[48000][640] @ W_out^T + b_out
// CTA 128x128, BK=64 (128B rows, SW128), double-buffered cp.async.
#define JSTAGE   65536
#define JOFF_AH  0
#define JOFF_AL  16384
#define JOFF_BH  32768
#define JOFF_BL  49152
#define JSM_TOTAL (2 * JSTAGE)   // 131072
#define JNK      10              // 640 / 64

__device__ __forceinline__ void jload(uint32_t sb, int stage, int m0, int n0, int kt,
                                      const __nv_bfloat16* __restrict__ AH,
                                      const __nv_bfloat16* __restrict__ AL,
                                      const __nv_bfloat16* __restrict__ BH,
                                      const __nv_bfloat16* __restrict__ BL, int tid) {
    uint32_t base = sb + stage * JSTAGE;
    #pragma unroll
    for (int ii = 0; ii < 16; ii++) {
        const int mat = ii >> 2;                 // 0=AH 1=AL 2=BH 3=BL
        int idx = (ii & 3) * 256 + tid;
        int r = idx >> 3, c = idx & 7;
        const __nv_bfloat16* g = (mat == 0) ? AH : (mat == 1) ? AL : (mat == 2) ? BH : BL;
        int grow = (mat < 2 ? m0 : n0) + r;
        const char* src = (const char*)(g + (size_t)grow * JOINT_ + kt) + c * 16;
        uint32_t dst = base + mat * 16384 + SW128((uint32_t)(r * 128 + c * 16));
        cp_async16(dst, src);
    }
}

__global__ void __launch_bounds__(256, 1)
joint_gemm_mma(const __nv_bfloat16* __restrict__ AH, const __nv_bfloat16* __restrict__ AL,
               const __nv_bfloat16* __restrict__ BH, const __nv_bfloat16* __restrict__ BL,
               const float* __restrict__ bias, float* __restrict__ C) {
    extern __shared__ char smem[];
    uint32_t sb = smem_u32(smem);
    const int tid = threadIdx.x, lane = tid & 31, wid = tid >> 5;
    const int m0 = blockIdx.y * 128, n0 = blockIdx.x * 128;
    const int m_warp = (wid >> 1) * 32;        // 0,32,64,96
    const int n_warp = (wid & 1) * 64;         // 0,64

    float acc[2][8][4];
    #pragma unroll
    for (int mf = 0; mf < 2; mf++)
        #pragma unroll
        for (int nf = 0; nf < 8; nf++)
            #pragma unroll
            for (int q = 0; q < 4; q++) acc[mf][nf][q] = 0.f;

    jload(sb, 0, m0, n0, 0, AH, AL, BH, BL, tid);
    cp_commit();

    // precomputed intra-warp ldmatrix offsets (byte offsets before k-chunk shift)
    const int a_row = (lane & 15);
    const uint32_t a_cb = (uint32_t)((lane >> 4) << 4);
    const int b_row = (lane & 7) + ((lane & 16) >> 1);
    const uint32_t b_cb = (uint32_t)(((lane >> 3) & 1) << 4);

    for (int kc = 0; kc < JNK; kc++) {
        int p = kc & 1;
        if (kc + 1 < JNK) {
            jload(sb, p ^ 1, m0, n0, (kc + 1) * 64, AH, AL, BH, BL, tid);
            cp_commit();
            cp_wait<1>();
        } else {
            cp_wait<0>();
        }
        __syncthreads();
        uint32_t base = sb + p * JSTAGE;
        #pragma unroll
        for (int kk = 0; kk < 4; kk++) {
            uint32_t aH[8], aL[8], bH[16], bL[16];
            #pragma unroll
            for (int mf = 0; mf < 2; mf++) {
                uint32_t off = SW128((uint32_t)((m_warp + mf * 16 + a_row) * 128) + kk * 32 + a_cb);
                ldmx4(&aH[mf * 4], base + JOFF_AH + off);
                ldmx4(&aL[mf * 4], base + JOFF_AL + off);
            }
            #pragma unroll
            for (int nf2 = 0; nf2 < 4; nf2++) {
                uint32_t off = SW128((uint32_t)((n_warp + nf2 * 16 + b_row) * 128) + kk * 32 + b_cb);
                ldmx4(&bH[nf2 * 4], base + JOFF_BH + off);
                ldmx4(&bL[nf2 * 4], base + JOFF_BL + off);
            }
            #pragma unroll
            for (int mf = 0; mf < 2; mf++)
                #pragma unroll
                for (int nf = 0; nf < 8; nf++) {
                    mma16816(acc[mf][nf], &aH[mf * 4], &bH[nf * 2]);
                    mma16816(acc[mf][nf], &aH[mf * 4], &bL[nf * 2]);
                    mma16816(acc[mf][nf], &aL[mf * 4], &bH[nf * 2]);
                }
        }
        __syncthreads();
    }

    // epilogue: C fragment thread mapping for m16n8: rows l/4 and l/4+8, cols 2*(l%4)
    #pragma unroll
    for (int nf = 0; nf < 8; nf++) {
        int col = n0 + n_warp + nf * 8 + 2 * (lane & 3);
        float b0 = __ldg(&bias[col]);
        float b1 = __ldg(&bias[col + 1]);
        #pragma unroll
        for (int mf = 0; mf < 2; mf++) {
            int row = m0 + m_warp + mf * 16 + (lane >> 2);
            float2 v0 = make_float2(acc[mf][nf][0] + b0, acc[mf][nf][1] + b1);
            float2 v1 = make_float2(acc[mf][nf][2] + b0, acc[mf][nf][3] + b1);
            *(float2*)(C + (size_t)row * ODIM + col) = v0;
            *(float2*)(C + (size_t)(row + 8) * ODIM + col) = v1;
        }
    }
}

// ---------------- launcher ----------------
extern "C" void kernel_launch(void* const* d_in, const int* in_sizes, int n_in,
                              void* d_out, int out_size) {
    const float* hs_pad = (const float*)d_in[0];
    const int*   ys     = (const int*)  d_in[1];
    const float* embW   = (const float*)d_in[2];
    const float* W_ih0  = (const float*)d_in[3];
    const float* W_hh0  = (const float*)d_in[4];
    const float* b_ih0  = (const float*)d_in[5];
    const float* b_hh0  = (const float*)d_in[6];
    const float* W_ih1  = (const float*)d_in[7];
    const float* W_hh1  = (const float*)d_in[8];
    const float* b_ih1  = (const float*)d_in[9];
    const float* b_hh1  = (const float*)d_in[10];
    const float* W_enc  = (const float*)d_in[11];
    const float* b_enc  = (const float*)d_in[12];
    const float* W_dec  = (const float*)d_in[13];
    const float* b_dec  = (const float*)d_in[14];
    const float* W_out  = (const float*)d_in[15];
    const float* b_out  = (const float*)d_in[16];
    float* out = (float*)d_out;

    float *p_eys, *p_X0, *p_h0, *p_h1, *p_hdec, *p_enc, *p_dec;
    float *p_Wih0T, *p_WencT, *p_WdecT;
    __nv_bfloat16 *p_jntH, *p_jntL, *p_WoutH, *p_WoutL;
    cudaGetSymbolAddress((void**)&p_eys, g_eys);
    cudaGetSymbolAddress((void**)&p_X0, g_X0);
    cudaGetSymbolAddress((void**)&p_h0, g_h0);
    cudaGetSymbolAddress((void**)&p_h1, g_h1);
    cudaGetSymbolAddress((void**)&p_hdec, g_hdec);
    cudaGetSymbolAddress((void**)&p_enc, g_enc);
    cudaGetSymbolAddress((void**)&p_dec, g_dec);
    cudaGetSymbolAddress((void**)&p_Wih0T, g_Wih0T);
    cudaGetSymbolAddress((void**)&p_WencT, g_WencT);
    cudaGetSymbolAddress((void**)&p_WdecT, g_WdecT);
    cudaGetSymbolAddress((void**)&p_jntH, g_jntH);
    cudaGetSymbolAddress((void**)&p_jntL, g_jntL);
    cudaGetSymbolAddress((void**)&p_WoutH, g_WoutH);
    cudaGetSymbolAddress((void**)&p_WoutL, g_WoutL);

    cudaFuncSetAttribute(joint_gemm_mma, cudaFuncAttributeMaxDynamicSharedMemorySize, JSM_TOTAL);

    dim3 tb(32, 8);
    transpose_kernel<<<dim3(EMBED / 32, 4 * DUNITS / 32), tb>>>(W_ih0, p_Wih0T, 4 * DUNITS, EMBED);
    transpose_kernel<<<dim3(EPROJS / 32, JOINT_ / 32), tb>>>(W_enc, p_WencT, JOINT_, EPROJS);
    transpose_kernel<<<dim3(DUNITS / 32, JOINT_ / 32), tb>>>(W_dec, p_WdecT, JOINT_, DUNITS);
    split_wout_kernel<<<(ODIM * JOINT_ + 255) / 256, 256>>>(W_out);

    embed_kernel<<<U_ * B_, 128>>>(ys, embW);
    init_state_kernel<<<64, 256>>>();

    // X0 = eys @ W_ih0^T + b_ih0 + b_hh0
    gemm_f32x2<<<dim3(4 * DUNITS / 128, (U_ * B_ + 127) / 128), 256>>>(
        p_eys, p_Wih0T, b_ih0, b_hh0, p_X0, U_ * B_, 4 * DUNITS, EMBED);

    for (int u = 0; u < U_; u++) {
        int cur = u & 1, prev = cur ^ 1;
        lstm_cell0<<<128, 256>>>(W_hh0, p_h0 + prev * B_ * DUNITS, p_h0 + cur * B_ * DUNITS, u);
        lstm_cell1<<<128, 256>>>(W_ih1, W_hh1, b_ih1, b_hh1,
                                 p_h0 + cur * B_ * DUNITS,
                                 p_h1 + prev * B_ * DUNITS,
                                 p_h1 + cur * B_ * DUNITS, u);
    }

    gemm_f32x2<<<dim3(JOINT_ / 128, (B_ * T_ + 127) / 128), 256>>>(
        hs_pad, p_WencT, b_enc, nullptr, p_enc, B_ * T_, JOINT_, EPROJS);
    gemm_f32x2<<<dim3(JOINT_ / 128, (B_ * U_ + 127) / 128), 256>>>(
        p_hdec, p_WdecT, b_dec, nullptr, p_dec, B_ * U_, JOINT_, DUNITS);

    tanh_split_kernel<<<(MROWS * (JOINT_ / 8) + 255) / 256, 256>>>();

    joint_gemm_mma<<<dim3(ODIM / 128, MROWS / 128), 256, JSM_TOTAL>>>(
        p_jntH, p_jntL, p_WoutH, p_WoutL, b_out, out);
}

// round 7
// speedup vs baseline: 1.7127x; 1.0619x over previous
#include <cuda_runtime.h>
#include <cuda_bf16.h>
#include <cuda_fp16.h>
#include <math.h>
#include <stdint.h>

// Problem dims
#define B_      8
#define T_      150
#define U_      40
#define EPROJS  512
#define DUNITS  1024
#define EMBED   512
#define JOINT_  640
#define ODIM    1024

#define MROWS   (B_*T_*U_)     // 48000
#define NBLK    128            // persistent LSTM grid

// ---------------- device scratch (no allocation allowed) ----------------
__device__ float g_eys  [U_*B_*EMBED];
__device__ float g_X0   [U_*B_*4*DUNITS];
__device__ float g_h0   [2*B_*DUNITS];
__device__ float g_h1   [2*B_*DUNITS];
__device__ float g_c0   [B_*DUNITS];
__device__ float g_c1   [B_*DUNITS];
__device__ float g_hdec [B_*U_*DUNITS];
__device__ float g_enc  [B_*T_*JOINT_];
__device__ float g_dec  [B_*U_*JOINT_];
__device__ float g_Wih0T[EMBED*4*DUNITS];
__device__ float g_WencT[EPROJS*JOINT_];
__device__ float g_WdecT[DUNITS*JOINT_];
// fp16 operands for the tensor-core joint GEMM
__device__ __align__(16) __half g_jntF [MROWS*JOINT_];
__device__ __align__(16) __half g_WoutH[ODIM*JOINT_];
__device__ __align__(16) __half g_WoutL[ODIM*JOINT_];
// grid barrier state
__device__ unsigned g_bar_count;
__device__ unsigned g_bar_sense;

// ---------------- f32x2 helpers ----------------
__device__ __forceinline__ unsigned long long pk2(float lo, float hi) {
    unsigned long long r;
    asm("mov.b64 %0, {%1, %2};" : "=l"(r) : "f"(lo), "f"(hi));
    return r;
}
__device__ __forceinline__ unsigned long long fma2(unsigned long long a,
                                                   unsigned long long b,
                                                   unsigned long long c) {
    unsigned long long d;
    asm("fma.rn.f32x2 %0, %1, %2, %3;" : "=l"(d) : "l"(a), "l"(b), "l"(c));
    return d;
}
__device__ __forceinline__ float2 upk2(unsigned long long v) {
    float2 r;
    asm("mov.b64 {%0, %1}, %2;" : "=f"(r.x), "=f"(r.y) : "l"(v));
    return r;
}
__device__ __forceinline__ float sigmf(float x) { return 1.0f / (1.0f + __expf(-x)); }

// ---------------- misc helpers ----------------
__device__ __forceinline__ uint32_t smem_u32(const void* p) {
    uint32_t a;
    asm("{ .reg .u64 t; cvta.to.shared.u64 t, %1; cvt.u32.u64 %0, t; }" : "=r"(a) : "l"(p));
    return a;
}
#define SW128(off) ((off) ^ (((off) >> 3) & 0x70))

__device__ __forceinline__ void cp_async16(uint32_t dst, const void* src) {
    asm volatile("cp.async.cg.shared.global [%0], [%1], 16;" :: "r"(dst), "l"(src));
}
__device__ __forceinline__ void cp_commit() { asm volatile("cp.async.commit_group;" ::: "memory"); }
template<int N> __device__ __forceinline__ void cp_wait() {
    asm volatile("cp.async.wait_group %0;" :: "n"(N) : "memory");
}
__device__ __forceinline__ void ldmx4(uint32_t* r, uint32_t addr) {
    asm volatile("ldmatrix.sync.aligned.m8n8.x4.shared.b16 {%0,%1,%2,%3}, [%4];"
                 : "=r"(r[0]), "=r"(r[1]), "=r"(r[2]), "=r"(r[3]) : "r"(addr));
}
__device__ __forceinline__ void mma16816h(float* c, const uint32_t* a, const uint32_t* b) {
    asm volatile(
        "mma.sync.aligned.m16n8k16.row.col.f32.f16.f16.f32 "
        "{%0,%1,%2,%3}, {%4,%5,%6,%7}, {%8,%9}, {%0,%1,%2,%3};"
        : "+f"(c[0]), "+f"(c[1]), "+f"(c[2]), "+f"(c[3])
        : "r"(a[0]), "r"(a[1]), "r"(a[2]), "r"(a[3]), "r"(b[0]), "r"(b[1]));
}
__device__ __forceinline__ unsigned ld_acq(unsigned* p) {
    unsigned v;
    asm volatile("ld.acquire.gpu.u32 %0, [%1];" : "=r"(v) : "l"(p) : "memory");
    return v;
}
__device__ __forceinline__ unsigned atom_add_acqrel(unsigned* p, unsigned v) {
    unsigned old;
    asm volatile("atom.acq_rel.gpu.add.u32 %0, [%1], %2;" : "=r"(old) : "l"(p), "r"(v) : "memory");
    return old;
}
__device__ __forceinline__ void red_add_release(unsigned* p, unsigned v) {
    asm volatile("red.release.gpu.add.u32 [%0], %1;" :: "l"(p), "r"(v) : "memory");
}

// ---------------- transpose ----------------
__global__ void transpose_kernel(const float* __restrict__ W, float* __restrict__ Wt,
                                 int N, int K) {
    __shared__ float t[32][33];
    int kb = blockIdx.x * 32, nb = blockIdx.y * 32;
    int x = threadIdx.x, y = threadIdx.y;
    #pragma unroll
    for (int yy = y; yy < 32; yy += 8) {
        int n = nb + yy, k = kb + x;
        if (n < N && k < K) t[yy][x] = W[(size_t)n * K + k];
    }
    __syncthreads();
    #pragma unroll
    for (int yy = y; yy < 32; yy += 8) {
        int k = kb + yy, n = nb + x;
        if (k < K && n < N) Wt[(size_t)k * N + n] = t[x][yy];
    }
}

// ---------------- embedding gather ----------------
__global__ void embed_kernel(const int* __restrict__ ys, const float* __restrict__ embW) {
    int row = blockIdx.x;            // u*8 + b
    int u = row >> 3, b = row & 7;
    int tok = ys[b * U_ + u];
    const float4* src = (const float4*)(embW + (size_t)tok * EMBED);
    float4* dst = (float4*)(g_eys + (size_t)row * EMBED);
    for (int i = threadIdx.x; i < EMBED / 4; i += blockDim.x) dst[i] = src[i];
}

__global__ void init_state_kernel() {
    int i = blockIdx.x * blockDim.x + threadIdx.x;
    if (i == 0) g_bar_count = 0;
    if (i < 2 * B_ * DUNITS) { g_h0[i] = 0.f; g_h1[i] = 0.f; }
    if (i < B_ * DUNITS)     { g_c0[i] = 0.f; g_c1[i] = 0.f; }
}

// ---------------- split W_out to fp16 hi/lo ----------------
__global__ void split_wout_kernel(const float* __restrict__ W) {
    int i = blockIdx.x * blockDim.x + threadIdx.x;
    if (i < ODIM * JOINT_) {
        float w = W[i];
        __half h = __float2half_rn(w);
        g_WoutH[i] = h;
        g_WoutL[i] = __float2half_rn(w - __half2float(h));
    }
}

// ---------------- fp32 GEMM via FFMA2 (small GEMMs) ----------------
__global__ __launch_bounds__(256, 2)
void gemm_f32x2(const float* __restrict__ A, const float* __restrict__ Wt,
                const float* __restrict__ bias1, const float* __restrict__ bias2,
                float* __restrict__ C, int M, int N, int K) {
    __shared__ float As[128][16];
    __shared__ float Bs[16][128];
    const int tid = threadIdx.x;
    const int m0 = blockIdx.y * 128;
    const int n0 = blockIdx.x * 128;
    const int tr = tid >> 4;
    const int tc = tid & 15;
    const int lr = tid >> 2;
    const int lk = (tid & 3) << 2;
    const int kr = tid >> 5;
    const int kc = (tid & 31) << 2;

    unsigned long long acc[8][4];
    #pragma unroll
    for (int i = 0; i < 8; i++)
        #pragma unroll
        for (int p = 0; p < 4; p++) acc[i][p] = 0ull;

    for (int kt = 0; kt < K; kt += 16) {
        #pragma unroll
        for (int h = 0; h < 2; h++) {
            int m = lr + h * 64;
            int gm = m0 + m;
            float4 v = make_float4(0.f, 0.f, 0.f, 0.f);
            if (gm < M) v = *(const float4*)(A + (size_t)gm * K + kt + lk);
            *(float4*)(&As[m][lk]) = v;
            int k = kr + h * 8;
            float4 w = *(const float4*)(Wt + (size_t)(kt + k) * N + n0 + kc);
            *(float4*)(&Bs[k][kc]) = w;
        }
        __syncthreads();
        const float* ap = &As[tr * 8][0];
        const float4* bp = (const float4*)&Bs[0][tc * 8];
        #pragma unroll
        for (int k = 0; k < 16; k++) {
            float4 bv0 = bp[k * 32];
            float4 bv1 = bp[k * 32 + 1];
            unsigned long long bpk[4];
            bpk[0] = pk2(bv0.x, bv0.y);
            bpk[1] = pk2(bv0.z, bv0.w);
            bpk[2] = pk2(bv1.x, bv1.y);
            bpk[3] = pk2(bv1.z, bv1.w);
            #pragma unroll
            for (int i = 0; i < 8; i++) {
                float a = ap[i * 16 + k];
                unsigned long long a2 = pk2(a, a);
                #pragma unroll
                for (int p = 0; p < 4; p++) acc[i][p] = fma2(a2, bpk[p], acc[i][p]);
            }
        }
        __syncthreads();
    }
    float bias[8];
    #pragma unroll
    for (int i = 0; i < 8; i++) {
        int n = n0 + tc * 8 + i;
        float bb = bias1[n];
        if (bias2) bb += bias2[n];
        bias[i] = bb;
    }
    #pragma unroll
    for (int i = 0; i < 8; i++) {
        int gm = m0 + tr * 8 + i;
        if (gm < M) {
            float2 v0 = upk2(acc[i][0]);
            float2 v1 = upk2(acc[i][1]);
            float2 v2 = upk2(acc[i][2]);
            float2 v3 = upk2(acc[i][3]);
            float4 o0 = make_float4(v0.x + bias[0], v0.y + bias[1], v1.x + bias[2], v1.y + bias[3]);
            float4 o1 = make_float4(v2.x + bias[4], v2.y + bias[5], v3.x + bias[6], v3.y + bias[7]);
            float* cp = C + (size_t)gm * N + n0 + tc * 8;
            *(float4*)cp = o0;
            *(float4*)(cp + 4) = o1;
        }
    }
}

// ---------------- persistent LSTM (single kernel, software grid barrier) ----------------
__device__ __forceinline__ void lstm_load_h(float* hs, const float* __restrict__ src, int tid) {
    const float4* s = (const float4*)src;
    float4* d = (float4*)hs;
    #pragma unroll
    for (int i = 0; i < 8; i++) d[tid + 256 * i] = s[tid + 256 * i];
}

__device__ __forceinline__ void lstm_accum(float acc[4][8], const float* __restrict__ W,
                                           const float4* hs4, int j, int lane) {
    const float4* W4 = (const float4*)W;
    #pragma unroll 2
    for (int k0 = 0; k0 < 256; k0 += 32) {
        float4 w[4];
        #pragma unroll
        for (int r = 0; r < 4; r++)
            w[r] = __ldg(&W4[(size_t)(r * DUNITS + j) * 256 + k0 + lane]);
        #pragma unroll
        for (int b = 0; b < 8; b++) {
            float4 hv = hs4[b * 256 + k0 + lane];
            #pragma unroll
            for (int r = 0; r < 4; r++)
                acc[r][b] += w[r].x * hv.x + w[r].y * hv.y + w[r].z * hv.z + w[r].w * hv.w;
        }
    }
}

__device__ __forceinline__ void lstm_reduce(float acc[4][8]) {
    #pragma unroll
    for (int r = 0; r < 4; r++)
        #pragma unroll
        for (int b = 0; b < 8; b++)
            #pragma unroll
            for (int off = 16; off; off >>= 1)
                acc[r][b] += __shfl_xor_sync(0xffffffffu, acc[r][b], off);
}

__device__ __forceinline__ void grid_sync_(unsigned& gen) {
    __threadfence();
    __syncthreads();
    if (threadIdx.x == 0) {
        if (atom_add_acqrel(&g_bar_count, 1) == NBLK - 1) {
            g_bar_count = 0;
            red_add_release(&g_bar_sense, 1);
        } else {
            while (ld_acq(&g_bar_sense) == gen) { __nanosleep(64); }
        }
    }
    __syncthreads();
    gen++;
}

__global__ __launch_bounds__(256, 1)
void lstm_persistent(const float* __restrict__ Whh0,
                     const float* __restrict__ Wih1, const float* __restrict__ Whh1,
                     const float* __restrict__ bih1, const float* __restrict__ bhh1) {
    __shared__ float hs[B_ * DUNITS];
    int tid = threadIdx.x, lane = tid & 31, warp = tid >> 5;
    int j = blockIdx.x * 8 + warp;
    unsigned gen = ld_acq(&g_bar_sense);   // stable at kernel start

    for (int u = 0; u < U_; u++) {
        int cur = u & 1, prev = cur ^ 1;
        const float* h0prev = g_h0 + prev * B_ * DUNITS;
        float* h0cur = g_h0 + cur * B_ * DUNITS;
        const float* h1prev = g_h1 + prev * B_ * DUNITS;
        float* h1cur = g_h1 + cur * B_ * DUNITS;

        // -------- cell 0 --------
        lstm_load_h(hs, h0prev, tid);
        __syncthreads();
        {
            float acc[4][8];
            #pragma unroll
            for (int r = 0; r < 4; r++)
                #pragma unroll
                for (int b = 0; b < 8; b++) acc[r][b] = 0.f;
            lstm_accum(acc, Whh0, (const float4*)hs, j, lane);
            lstm_reduce(acc);
            if (lane < 8) {
                int b = lane;
                const float* x0 = &g_X0[(size_t)(u * 8 + b) * 4 * DUNITS];
                float gi = acc[0][b] + x0[j];
                float gf = acc[1][b] + x0[DUNITS + j];
                float gg = acc[2][b] + x0[2 * DUNITS + j];
                float go = acc[3][b] + x0[3 * DUNITS + j];
                float c = g_c0[b * DUNITS + j];
                float cn = sigmf(gf) * c + sigmf(gi) * tanhf(gg);
                float hn = sigmf(go) * tanhf(cn);
                g_c0[b * DUNITS + j] = cn;
                h0cur[b * DUNITS + j] = hn;
            }
        }
        grid_sync_(gen);

        // -------- cell 1 --------
        {
            float acc[4][8];
            #pragma unroll
            for (int r = 0; r < 4; r++)
                #pragma unroll
                for (int b = 0; b < 8; b++) acc[r][b] = 0.f;
            lstm_load_h(hs, h0cur, tid);
            __syncthreads();
            lstm_accum(acc, Wih1, (const float4*)hs, j, lane);
            __syncthreads();
            lstm_load_h(hs, h1prev, tid);
            __syncthreads();
            lstm_accum(acc, Whh1, (const float4*)hs, j, lane);
            lstm_reduce(acc);
            if (lane < 8) {
                int b = lane;
                float gi = acc[0][b] + bih1[j] + bhh1[j];
                float gf = acc[1][b] + bih1[DUNITS + j] + bhh1[DUNITS + j];
                float gg = acc[2][b] + bih1[2 * DUNITS + j] + bhh1[2 * DUNITS + j];
                float go = acc[3][b] + bih1[3 * DUNITS + j] + bhh1[3 * DUNITS + j];
                float c = g_c1[b * DUNITS + j];
                float cn = sigmf(gf) * c + sigmf(gi) * tanhf(gg);
                float hn = sigmf(go) * tanhf(cn);
                g_c1[b * DUNITS + j] = cn;
                h1cur[b * DUNITS + j] = hn;
                g_hdec[(size_t)(b * U_ + u) * DUNITS + j] = hn;
            }
        }
        if (u + 1 < U_) grid_sync_(gen);
    }
}

// ---------------- joint tanh -> fp16 ----------------
__global__ void tanh_split_kernel() {
    int idx = blockIdx.x * blockDim.x + threadIdx.x;     // per 8 elements
    const int TOT8 = MROWS * (JOINT_ / 8);               // 3,840,000
    if (idx >= TOT8) return;
    int row = idx / (JOINT_ / 8);
    int j8 = idx - row * (JOINT_ / 8);
    int u = row % U_;
    int bt = row / U_;
    int b = bt / T_;
    const float4* e4 = (const float4*)&g_enc[(size_t)bt * JOINT_ + j8 * 8];
    const float4* d4 = (const float4*)&g_dec[(size_t)(b * U_ + u) * JOINT_ + j8 * 8];
    __half2 hp[4];
    #pragma unroll
    for (int q = 0; q < 2; q++) {
        float4 e = e4[q], d = d4[q];
        hp[q * 2 + 0] = __floats2half2_rn(tanhf(e.x + d.x), tanhf(e.y + d.y));
        hp[q * 2 + 1] = __floats2half2_rn(tanhf(e.z + d.z), tanhf(e.w + d.w));
    }
    *(uint4*)&g_jntF[(size_t)row * JOINT_ + j8 * 8] = *(uint4*)hp;
}

// ---------------- joint GEMM: 2-pass fp16 mma.sync, 3-stage cp.async ----------------
// C[48000][1024] = A_f16 @ (W_outH + W_outL)^T + b_out
#define JSTAGE   49152
#define JOFF_A   0
#define JOFF_BH  16384
#define JOFF_BL  32768
#define JSM_TOTAL (3 * JSTAGE)   // 147456
#define JNK      10              // 640 / 64

__device__ __forceinline__ void jload(uint32_t sb, int stage, int m0, int n0, int kt,
                                      const __half* __restrict__ AF,
                                      const __half* __restrict__ BH,
                                      const __half* __restrict__ BL, int tid) {
    uint32_t base = sb + stage * JSTAGE;
    #pragma unroll
    for (int ii = 0; ii < 12; ii++) {
        const int mat = ii >> 2;                 // 0=A 1=BH 2=BL
        int idx = (ii & 3) * 256 + tid;
        int r = idx >> 3, c = idx & 7;
        const __half* g = (mat == 0) ? AF : (mat == 1) ? BH : BL;
        int grow = (mat == 0 ? m0 : n0) + r;
        const char* src = (const char*)(g + (size_t)grow * JOINT_ + kt) + c * 16;
        uint32_t dst = base + mat * 16384 + SW128((uint32_t)(r * 128 + c * 16));
        cp_async16(dst, src);
    }
}

__global__ void __launch_bounds__(256, 1)
joint_gemm_mma(const __half* __restrict__ AF,
               const __half* __restrict__ BH, const __half* __restrict__ BL,
               const float* __restrict__ bias, float* __restrict__ C) {
    extern __shared__ char smem[];
    uint32_t sb = smem_u32(smem);
    const int tid = threadIdx.x, lane = tid & 31, wid = tid >> 5;
    const int m0 = blockIdx.y * 128, n0 = blockIdx.x * 128;
    const int m_warp = (wid >> 1) * 32;        // 0,32,64,96
    const int n_warp = (wid & 1) * 64;         // 0,64

    float acc[2][8][4];
    #pragma unroll
    for (int mf = 0; mf < 2; mf++)
        #pragma unroll
        for (int nf = 0; nf < 8; nf++)
            #pragma unroll
            for (int q = 0; q < 4; q++) acc[mf][nf][q] = 0.f;

    jload(sb, 0, m0, n0, 0, AF, BH, BL, tid);
    cp_commit();
    jload(sb, 1, m0, n0, 64, AF, BH, BL, tid);
    cp_commit();

    const int a_row = (lane & 15);
    const uint32_t a_cb = (uint32_t)((lane >> 4) << 4);
    const int b_row = (lane & 7) + ((lane & 16) >> 1);
    const uint32_t b_cb = (uint32_t)(((lane >> 3) & 1) << 4);

    for (int kc = 0; kc < JNK; kc++) {
        __syncthreads();            // all warps done reading the stage we refill below
        if (kc + 2 < JNK) {
            jload(sb, (kc + 2) % 3, m0, n0, (kc + 2) * 64, AF, BH, BL, tid);
            cp_commit();
            cp_wait<2>();
        } else {
            cp_wait<0>();
        }
        __syncthreads();            // stage kc data visible
        uint32_t base = sb + (kc % 3) * JSTAGE;
        #pragma unroll
        for (int kk = 0; kk < 4; kk++) {
            uint32_t aF[8], bH[16], bL[16];
            #pragma unroll
            for (int mf = 0; mf < 2; mf++) {
                uint32_t off = SW128((uint32_t)((m_warp + mf * 16 + a_row) * 128) + kk * 32 + a_cb);
                ldmx4(&aF[mf * 4], base + JOFF_A + off);
            }
            #pragma unroll
            for (int nf2 = 0; nf2 < 4; nf2++) {
                uint32_t off = SW128((uint32_t)((n_warp + nf2 * 16 + b_row) * 128) + kk * 32 + b_cb);
                ldmx4(&bH[nf2 * 4], base + JOFF_BH + off);
                ldmx4(&bL[nf2 * 4], base + JOFF_BL + off);
            }
            #pragma unroll
            for (int mf = 0; mf < 2; mf++)
                #pragma unroll
                for (int nf = 0; nf < 8; nf++) {
                    mma16816h(acc[mf][nf], &aF[mf * 4], &bH[nf * 2]);
                    mma16816h(acc[mf][nf], &aF[mf * 4], &bL[nf * 2]);
                }
        }
    }

    // epilogue: m16n8 C map — rows l/4, l/4+8; cols 2*(l%4)
    #pragma unroll
    for (int nf = 0; nf < 8; nf++) {
        int col = n0 + n_warp + nf * 8 + 2 * (lane & 3);
        float b0 = __ldg(&bias[col]);
        float b1 = __ldg(&bias[col + 1]);
        #pragma unroll
        for (int mf = 0; mf < 2; mf++) {
            int row = m0 + m_warp + mf * 16 + (lane >> 2);
            float2 v0 = make_float2(acc[mf][nf][0] + b0, acc[mf][nf][1] + b1);
            float2 v1 = make_float2(acc[mf][nf][2] + b0, acc[mf][nf][3] + b1);
            *(float2*)(C + (size_t)row * ODIM + col) = v0;
            *(float2*)(C + (size_t)(row + 8) * ODIM + col) = v1;
        }
    }
}

// ---------------- launcher ----------------
extern "C" void kernel_launch(void* const* d_in, const int* in_sizes, int n_in,
                              void* d_out, int out_size) {
    const float* hs_pad = (const float*)d_in[0];
    const int*   ys     = (const int*)  d_in[1];
    const float* embW   = (const float*)d_in[2];
    const float* W_ih0  = (const float*)d_in[3];
    const float* W_hh0  = (const float*)d_in[4];
    const float* b_ih0  = (const float*)d_in[5];
    const float* b_hh0  = (const float*)d_in[6];
    const float* W_ih1  = (const float*)d_in[7];
    const float* W_hh1  = (const float*)d_in[8];
    const float* b_ih1  = (const float*)d_in[9];
    const float* b_hh1  = (const float*)d_in[10];
    const float* W_enc  = (const float*)d_in[11];
    const float* b_enc  = (const float*)d_in[12];
    const float* W_dec  = (const float*)d_in[13];
    const float* b_dec  = (const float*)d_in[14];
    const float* W_out  = (const float*)d_in[15];
    const float* b_out  = (const float*)d_in[16];
    float* out = (float*)d_out;

    float *p_eys, *p_X0, *p_hdec, *p_enc, *p_dec;
    float *p_Wih0T, *p_WencT, *p_WdecT;
    __half *p_jntF, *p_WoutH, *p_WoutL;
    cudaGetSymbolAddress((void**)&p_eys, g_eys);
    cudaGetSymbolAddress((void**)&p_X0, g_X0);
    cudaGetSymbolAddress((void**)&p_hdec, g_hdec);
    cudaGetSymbolAddress((void**)&p_enc, g_enc);
    cudaGetSymbolAddress((void**)&p_dec, g_dec);
    cudaGetSymbolAddress((void**)&p_Wih0T, g_Wih0T);
    cudaGetSymbolAddress((void**)&p_WencT, g_WencT);
    cudaGetSymbolAddress((void**)&p_WdecT, g_WdecT);
    cudaGetSymbolAddress((void**)&p_jntF, g_jntF);
    cudaGetSymbolAddress((void**)&p_WoutH, g_WoutH);
    cudaGetSymbolAddress((void**)&p_WoutL, g_WoutL);

    cudaFuncSetAttribute(joint_gemm_mma, cudaFuncAttributeMaxDynamicSharedMemorySize, JSM_TOTAL);

    dim3 tb(32, 8);
    transpose_kernel<<<dim3(EMBED / 32, 4 * DUNITS / 32), tb>>>(W_ih0, p_Wih0T, 4 * DUNITS, EMBED);
    transpose_kernel<<<dim3(EPROJS / 32, JOINT_ / 32), tb>>>(W_enc, p_WencT, JOINT_, EPROJS);
    transpose_kernel<<<dim3(DUNITS / 32, JOINT_ / 32), tb>>>(W_dec, p_WdecT, JOINT_, DUNITS);
    split_wout_kernel<<<(ODIM * JOINT_ + 255) / 256, 256>>>(W_out);

    embed_kernel<<<U_ * B_, 128>>>(ys, embW);
    init_state_kernel<<<64, 256>>>();

    // X0 = eys @ W_ih0^T + b_ih0 + b_hh0
    gemm_f32x2<<<dim3(4 * DUNITS / 128, (U_ * B_ + 127) / 128), 256>>>(
        p_eys, p_Wih0T, b_ih0, b_hh0, p_X0, U_ * B_, 4 * DUNITS, EMBED);

    // whole 40-step 2-layer LSTM in one persistent kernel
    lstm_persistent<<<NBLK, 256>>>(W_hh0, W_ih1, W_hh1, b_ih1, b_hh1);

    gemm_f32x2<<<dim3(JOINT_ / 128, (B_ * T_ + 127) / 128), 256>>>(
        hs_pad, p_WencT, b_enc, nullptr, p_enc, B_ * T_, JOINT_, EPROJS);
    gemm_f32x2<<<dim3(JOINT_ / 128, (B_ * U_ + 127) / 128), 256>>>(
        p_hdec, p_WdecT, b_dec, nullptr, p_dec, B_ * U_, JOINT_, DUNITS);

    tanh_split_kernel<<<(MROWS * (JOINT_ / 8) + 255) / 256, 256>>>();

    joint_gemm_mma<<<dim3(ODIM / 128, MROWS / 128), 256, JSM_TOTAL>>>(
        p_jntF, p_WoutH, p_WoutL, b_out, out);
}

// round 10
// speedup vs baseline: 2.0603x; 1.2030x over previous
#include <cuda_runtime.h>
#include <cuda_bf16.h>
#include <cuda_fp16.h>
#include <math.h>
#include <stdint.h>

// Problem dims
#define B_      8
#define T_      150
#define U_      40
#define EPROJS  512
#define DUNITS  1024
#define EMBED   512
#define JOINT_  640
#define ODIM    1024

#define MROWS   (B_*T_*U_)     // 48000
#define NBLK    128            // persistent LSTM grid

// ---------------- device scratch (no allocation allowed) ----------------
__device__ float g_eys  [U_*B_*EMBED];
__device__ float g_X0   [U_*B_*4*DUNITS];
__device__ float g_h0   [2*B_*DUNITS];
__device__ float g_h1   [2*B_*DUNITS];
__device__ float g_c0   [B_*DUNITS];
__device__ float g_c1   [B_*DUNITS];
__device__ float g_hdec [B_*U_*DUNITS];
__device__ float g_enc  [B_*T_*JOINT_];
__device__ float g_dec  [B_*U_*JOINT_];
__device__ float g_Wih0T[EMBED*4*DUNITS];
__device__ float g_WencT[EPROJS*JOINT_];
__device__ float g_WdecT[DUNITS*JOINT_];
// fp16 operands for the tensor-core joint GEMM
__device__ __align__(16) __half g_jntF [MROWS*JOINT_];
__device__ __align__(16) __half g_WoutF[ODIM*JOINT_];
// grid barrier state
__device__ unsigned g_bar_count;
__device__ unsigned g_bar_sense;

// ---------------- f32x2 helpers ----------------
__device__ __forceinline__ unsigned long long pk2(float lo, float hi) {
    unsigned long long r;
    asm("mov.b64 %0, {%1, %2};" : "=l"(r) : "f"(lo), "f"(hi));
    return r;
}
__device__ __forceinline__ unsigned long long fma2(unsigned long long a,
                                                   unsigned long long b,
                                                   unsigned long long c) {
    unsigned long long d;
    asm("fma.rn.f32x2 %0, %1, %2, %3;" : "=l"(d) : "l"(a), "l"(b), "l"(c));
    return d;
}
__device__ __forceinline__ float2 upk2(unsigned long long v) {
    float2 r;
    asm("mov.b64 {%0, %1}, %2;" : "=f"(r.x), "=f"(r.y) : "l"(v));
    return r;
}
__device__ __forceinline__ float sigmf(float x) { return 1.0f / (1.0f + __expf(-x)); }

// ---------------- misc helpers ----------------
__device__ __forceinline__ uint32_t smem_u32(const void* p) {
    uint32_t a;
    asm("{ .reg .u64 t; cvta.to.shared.u64 t, %1; cvt.u32.u64 %0, t; }" : "=r"(a) : "l"(p));
    return a;
}
#define SW128(off) ((off) ^ (((off) >> 3) & 0x70))

__device__ __forceinline__ void cp_async16(uint32_t dst, const void* src) {
    asm volatile("cp.async.cg.shared.global [%0], [%1], 16;" :: "r"(dst), "l"(src));
}
__device__ __forceinline__ void cp_commit() { asm volatile("cp.async.commit_group;" ::: "memory"); }
template<int N> __device__ __forceinline__ void cp_wait() {
    asm volatile("cp.async.wait_group %0;" :: "n"(N) : "memory");
}
__device__ __forceinline__ void ldmx4(uint32_t* r, uint32_t addr) {
    asm volatile("ldmatrix.sync.aligned.m8n8.x4.shared.b16 {%0,%1,%2,%3}, [%4];"
                 : "=r"(r[0]), "=r"(r[1]), "=r"(r[2]), "=r"(r[3]) : "r"(addr));
}
__device__ __forceinline__ void mma16816h(float* c, const uint32_t* a, const uint32_t* b) {
    asm volatile(
        "mma.sync.aligned.m16n8k16.row.col.f32.f16.f16.f32 "
        "{%0,%1,%2,%3}, {%4,%5,%6,%7}, {%8,%9}, {%0,%1,%2,%3};"
        : "+f"(c[0]), "+f"(c[1]), "+f"(c[2]), "+f"(c[3])
        : "r"(a[0]), "r"(a[1]), "r"(a[2]), "r"(a[3]), "r"(b[0]), "r"(b[1]));
}
__device__ __forceinline__ unsigned ld_acq(unsigned* p) {
    unsigned v;
    asm volatile("ld.acquire.gpu.u32 %0, [%1];" : "=r"(v) : "l"(p) : "memory");
    return v;
}
__device__ __forceinline__ unsigned atom_add_acqrel(unsigned* p, unsigned v) {
    unsigned old;
    asm volatile("atom.acq_rel.gpu.add.u32 %0, [%1], %2;" : "=r"(old) : "l"(p), "r"(v) : "memory");
    return old;
}
__device__ __forceinline__ void red_add_release(unsigned* p, unsigned v) {
    asm volatile("red.release.gpu.add.u32 [%0], %1;" :: "l"(p), "r"(v) : "memory");
}

// ---------------- transpose ----------------
__global__ void transpose_kernel(const float* __restrict__ W, float* __restrict__ Wt,
                                 int N, int K) {
    __shared__ float t[32][33];
    int kb = blockIdx.x * 32, nb = blockIdx.y * 32;
    int x = threadIdx.x, y = threadIdx.y;
    #pragma unroll
    for (int yy = y; yy < 32; yy += 8) {
        int n = nb + yy, k = kb + x;
        if (n < N && k < K) t[yy][x] = W[(size_t)n * K + k];
    }
    __syncthreads();
    #pragma unroll
    for (int yy = y; yy < 32; yy += 8) {
        int k = kb + yy, n = nb + x;
        if (k < K && n < N) Wt[(size_t)k * N + n] = t[x][yy];
    }
}

// ---------------- embedding gather ----------------
__global__ void embed_kernel(const int* __restrict__ ys, const float* __restrict__ embW) {
    int row = blockIdx.x;            // u*8 + b
    int u = row >> 3, b = row & 7;
    int tok = ys[b * U_ + u];
    const float4* src = (const float4*)(embW + (size_t)tok * EMBED);
    float4* dst = (float4*)(g_eys + (size_t)row * EMBED);
    for (int i = threadIdx.x; i < EMBED / 4; i += blockDim.x) dst[i] = src[i];
}

__global__ void init_state_kernel() {
    int i = blockIdx.x * blockDim.x + threadIdx.x;
    if (i == 0) g_bar_count = 0;
    if (i < 2 * B_ * DUNITS) { g_h0[i] = 0.f; g_h1[i] = 0.f; }
    if (i < B_ * DUNITS)     { g_c0[i] = 0.f; g_c1[i] = 0.f; }
}

// ---------------- convert W_out to fp16 ----------------
__global__ void conv_wout_kernel(const float* __restrict__ W) {
    int i = blockIdx.x * blockDim.x + threadIdx.x;
    if (i < ODIM * JOINT_ / 2) {
        float2 w = ((const float2*)W)[i];
        ((__half2*)g_WoutF)[i] = __floats2half2_rn(w.x, w.y);
    }
}

// ---------------- fp32 GEMM core via FFMA2 ----------------
__device__ __forceinline__
void gemm_core(const float* __restrict__ A, const float* __restrict__ Wt,
               const float* __restrict__ bias1, const float* __restrict__ bias2,
               float* __restrict__ C, int M, int N, int K, int m0, int n0) {
    __shared__ float As[128][16];
    __shared__ float Bs[16][128];
    const int tid = threadIdx.x;
    const int tr = tid >> 4;
    const int tc = tid & 15;
    const int lr = tid >> 2;
    const int lk = (tid & 3) << 2;
    const int kr = tid >> 5;
    const int kc = (tid & 31) << 2;

    unsigned long long acc[8][4];
    #pragma unroll
    for (int i = 0; i < 8; i++)
        #pragma unroll
        for (int p = 0; p < 4; p++) acc[i][p] = 0ull;

    for (int kt = 0; kt < K; kt += 16) {
        #pragma unroll
        for (int h = 0; h < 2; h++) {
            int m = lr + h * 64;
            int gm = m0 + m;
            float4 v = make_float4(0.f, 0.f, 0.f, 0.f);
            if (gm < M) v = *(const float4*)(A + (size_t)gm * K + kt + lk);
            *(float4*)(&As[m][lk]) = v;
            int k = kr + h * 8;
            float4 w = *(const float4*)(Wt + (size_t)(kt + k) * N + n0 + kc);
            *(float4*)(&Bs[k][kc]) = w;
        }
        __syncthreads();
        const float* ap = &As[tr * 8][0];
        const float4* bp = (const float4*)&Bs[0][tc * 8];
        #pragma unroll
        for (int k = 0; k < 16; k++) {
            float4 bv0 = bp[k * 32];
            float4 bv1 = bp[k * 32 + 1];
            unsigned long long bpk[4];
            bpk[0] = pk2(bv0.x, bv0.y);
            bpk[1] = pk2(bv0.z, bv0.w);
            bpk[2] = pk2(bv1.x, bv1.y);
            bpk[3] = pk2(bv1.z, bv1.w);
            #pragma unroll
            for (int i = 0; i < 8; i++) {
                float a = ap[i * 16 + k];
                unsigned long long a2 = pk2(a, a);
                #pragma unroll
                for (int p = 0; p < 4; p++) acc[i][p] = fma2(a2, bpk[p], acc[i][p]);
            }
        }
        __syncthreads();
    }
    float bias[8];
    #pragma unroll
    for (int i = 0; i < 8; i++) {
        int n = n0 + tc * 8 + i;
        float bb = bias1[n];
        if (bias2) bb += bias2[n];
        bias[i] = bb;
    }
    #pragma unroll
    for (int i = 0; i < 8; i++) {
        int gm = m0 + tr * 8 + i;
        if (gm < M) {
            float2 v0 = upk2(acc[i][0]);
            float2 v1 = upk2(acc[i][1]);
            float2 v2 = upk2(acc[i][2]);
            float2 v3 = upk2(acc[i][3]);
            float4 o0 = make_float4(v0.x + bias[0], v0.y + bias[1], v1.x + bias[2], v1.y + bias[3]);
            float4 o1 = make_float4(v2.x + bias[4], v2.y + bias[5], v3.x + bias[6], v3.y + bias[7]);
            float* cp = C + (size_t)gm * N + n0 + tc * 8;
            *(float4*)cp = o0;
            *(float4*)(cp + 4) = o1;
        }
    }
}

__global__ __launch_bounds__(256, 2)
void gemm_f32x2(const float* __restrict__ A, const float* __restrict__ Wt,
                const float* __restrict__ bias1, const float* __restrict__ bias2,
                float* __restrict__ C, int M, int N, int K) {
    gemm_core(A, Wt, bias1, bias2, C, M, N, K, blockIdx.y * 128, blockIdx.x * 128);
}

// fused enc_proj (blockIdx.y < 10) + dec_proj (blockIdx.y >= 10)
__global__ __launch_bounds__(256, 2)
void gemm_encdec(const float* __restrict__ hs_pad, const float* __restrict__ WencT,
                 const float* __restrict__ b_enc, float* __restrict__ enc_out,
                 const float* __restrict__ hdec, const float* __restrict__ WdecT,
                 const float* __restrict__ b_dec, float* __restrict__ dec_out) {
    if (blockIdx.y < 10) {
        gemm_core(hs_pad, WencT, b_enc, nullptr, enc_out,
                  B_ * T_, JOINT_, EPROJS, blockIdx.y * 128, blockIdx.x * 128);
    } else {
        gemm_core(hdec, WdecT, b_dec, nullptr, dec_out,
                  B_ * U_, JOINT_, DUNITS, (blockIdx.y - 10) * 128, blockIdx.x * 128);
    }
}

// ---------------- persistent LSTM (single kernel, software grid barrier) ----------------
__device__ __forceinline__ void lstm_load_h(float* hs, const float* __restrict__ src, int tid) {
    const float4* s = (const float4*)src;
    float4* d = (float4*)hs;
    #pragma unroll
    for (int i = 0; i < 8; i++) d[tid + 256 * i] = s[tid + 256 * i];
}

__device__ __forceinline__ void lstm_accum(float acc[4][8], const float* __restrict__ W,
                                           const float4* hs4, int j, int lane) {
    const float4* W4 = (const float4*)W;
    #pragma unroll 2
    for (int k0 = 0; k0 < 256; k0 += 32) {
        float4 w[4];
        #pragma unroll
        for (int r = 0; r < 4; r++)
            w[r] = __ldg(&W4[(size_t)(r * DUNITS + j) * 256 + k0 + lane]);
        #pragma unroll
        for (int b = 0; b < 8; b++) {
            float4 hv = hs4[b * 256 + k0 + lane];
            #pragma unroll
            for (int r = 0; r < 4; r++)
                acc[r][b] += w[r].x * hv.x + w[r].y * hv.y + w[r].z * hv.z + w[r].w * hv.w;
        }
    }
}

__device__ __forceinline__ void lstm_reduce(float acc[4][8]) {
    #pragma unroll
    for (int r = 0; r < 4; r++)
        #pragma unroll
        for (int b = 0; b < 8; b++)
            #pragma unroll
            for (int off = 16; off; off >>= 1)
                acc[r][b] += __shfl_xor_sync(0xffffffffu, acc[r][b], off);
}

__device__ __forceinline__ void grid_sync_(unsigned& gen) {
    __threadfence();
    __syncthreads();
    if (threadIdx.x == 0) {
        if (atom_add_acqrel(&g_bar_count, 1) == NBLK - 1) {
            g_bar_count = 0;
            red_add_release(&g_bar_sense, 1);
        } else {
            while (ld_acq(&g_bar_sense) == gen) { __nanosleep(64); }
        }
    }
    __syncthreads();
    gen++;
}

__global__ __launch_bounds__(256, 1)
void lstm_persistent(const float* __restrict__ Whh0,
                     const float* __restrict__ Wih1, const float* __restrict__ Whh1,
                     const float* __restrict__ bih1, const float* __restrict__ bhh1) {
    __shared__ float hs[B_ * DUNITS];
    int tid = threadIdx.x, lane = tid & 31, warp = tid >> 5;
    int j = blockIdx.x * 8 + warp;
    unsigned gen = ld_acq(&g_bar_sense);   // stable at kernel start

    for (int u = 0; u < U_; u++) {
        int cur = u & 1, prev = cur ^ 1;
        const float* h0prev = g_h0 + prev * B_ * DUNITS;
        float* h0cur = g_h0 + cur * B_ * DUNITS;
        const float* h1prev = g_h1 + prev * B_ * DUNITS;
        float* h1cur = g_h1 + cur * B_ * DUNITS;

        // -------- cell 0 --------
        lstm_load_h(hs, h0prev, tid);
        __syncthreads();
        {
            float acc[4][8];
            #pragma unroll
            for (int r = 0; r < 4; r++)
                #pragma unroll
                for (int b = 0; b < 8; b++) acc[r][b] = 0.f;
            lstm_accum(acc, Whh0, (const float4*)hs, j, lane);
            lstm_reduce(acc);
            if (lane < 8) {
                int b = lane;
                const float* x0 = &g_X0[(size_t)(u * 8 + b) * 4 * DUNITS];
                float gi = acc[0][b] + x0[j];
                float gf = acc[1][b] + x0[DUNITS + j];
                float gg = acc[2][b] + x0[2 * DUNITS + j];
                float go = acc[3][b] + x0[3 * DUNITS + j];
                float c = g_c0[b * DUNITS + j];
                float cn = sigmf(gf) * c + sigmf(gi) * tanhf(gg);
                float hn = sigmf(go) * tanhf(cn);
                g_c0[b * DUNITS + j] = cn;
                h0cur[b * DUNITS + j] = hn;
            }
        }
        grid_sync_(gen);

        // -------- cell 1 --------
        {
            float acc[4][8];
            #pragma unroll
            for (int r = 0; r < 4; r++)
                #pragma unroll
                for (int b = 0; b < 8; b++) acc[r][b] = 0.f;
            lstm_load_h(hs, h0cur, tid);
            __syncthreads();
            lstm_accum(acc, Wih1, (const float4*)hs, j, lane);
            __syncthreads();
            lstm_load_h(hs, h1prev, tid);
            __syncthreads();
            lstm_accum(acc, Whh1, (const float4*)hs, j, lane);
            lstm_reduce(acc);
            if (lane < 8) {
                int b = lane;
                float gi = acc[0][b] + bih1[j] + bhh1[j];
                float gf = acc[1][b] + bih1[DUNITS + j] + bhh1[DUNITS + j];
                float gg = acc[2][b] + bih1[2 * DUNITS + j] + bhh1[2 * DUNITS + j];
                float go = acc[3][b] + bih1[3 * DUNITS + j] + bhh1[3 * DUNITS + j];
                float c = g_c1[b * DUNITS + j];
                float cn = sigmf(gf) * c + sigmf(gi) * tanhf(gg);
                float hn = sigmf(go) * tanhf(cn);
                g_c1[b * DUNITS + j] = cn;
                h1cur[b * DUNITS + j] = hn;
                g_hdec[(size_t)(b * U_ + u) * DUNITS + j] = hn;
            }
        }
        if (u + 1 < U_) grid_sync_(gen);
    }
}

// ---------------- joint tanh -> fp16 ----------------
__global__ void tanh_split_kernel() {
    int idx = blockIdx.x * blockDim.x + threadIdx.x;     // per 8 elements
    const int TOT8 = MROWS * (JOINT_ / 8);               // 3,840,000
    if (idx >= TOT8) return;
    int row = idx / (JOINT_ / 8);
    int j8 = idx - row * (JOINT_ / 8);
    int u = row % U_;
    int bt = row / U_;
    int b = bt / T_;
    const float4* e4 = (const float4*)&g_enc[(size_t)bt * JOINT_ + j8 * 8];
    const float4* d4 = (const float4*)&g_dec[(size_t)(b * U_ + u) * JOINT_ + j8 * 8];
    __half2 hp[4];
    #pragma unroll
    for (int q = 0; q < 2; q++) {
        float4 e = e4[q], d = d4[q];
        hp[q * 2 + 0] = __floats2half2_rn(tanhf(e.x + d.x), tanhf(e.y + d.y));
        hp[q * 2 + 1] = __floats2half2_rn(tanhf(e.z + d.z), tanhf(e.w + d.w));
    }
    *(uint4*)&g_jntF[(size_t)row * JOINT_ + j8 * 8] = *(uint4*)hp;
}

// ---------------- joint GEMM: single-pass fp16 mma.sync, 3-stage cp.async ----------------
// C[48000][1024] = A_f16 @ W_outF^T + b_out
#define JSTAGE   32768
#define JOFF_A   0
#define JOFF_B   16384
#define JSM_TOTAL (3 * JSTAGE)   // 98304 -> 2 CTAs/SM
#define JNK      10              // 640 / 64

__device__ __forceinline__ void jload(uint32_t sb, int stage, int m0, int n0, int kt,
                                      const __half* __restrict__ AF,
                                      const __half* __restrict__ BF, int tid) {
    uint32_t base = sb + stage * JSTAGE;
    #pragma unroll
    for (int ii = 0; ii < 8; ii++) {
        const int mat = ii >> 2;                 // 0=A 1=B
        int idx = (ii & 3) * 256 + tid;
        int r = idx >> 3, c = idx & 7;
        const __half* g = (mat == 0) ? AF : BF;
        int grow = (mat == 0 ? m0 : n0) + r;
        const char* src = (const char*)(g + (size_t)grow * JOINT_ + kt) + c * 16;
        uint32_t dst = base + mat * 16384 + SW128((uint32_t)(r * 128 + c * 16));
        cp_async16(dst, src);
    }
}

__global__ void __launch_bounds__(256, 2)
joint_gemm_mma(const __half* __restrict__ AF, const __half* __restrict__ BF,
               const float* __restrict__ bias, float* __restrict__ C) {
    extern __shared__ char smem[];
    uint32_t sb = smem_u32(smem);
    const int tid = threadIdx.x, lane = tid & 31, wid = tid >> 5;
    const int m0 = blockIdx.y * 128, n0 = blockIdx.x * 128;
    const int m_warp = (wid >> 1) * 32;        // 0,32,64,96
    const int n_warp = (wid & 1) * 64;         // 0,64

    float acc[2][8][4];
    #pragma unroll
    for (int mf = 0; mf < 2; mf++)
        #pragma unroll
        for (int nf = 0; nf < 8; nf++)
            #pragma unroll
            for (int q = 0; q < 4; q++) acc[mf][nf][q] = 0.f;

    jload(sb, 0, m0, n0, 0, AF, BF, tid);
    cp_commit();
    jload(sb, 1, m0, n0, 64, AF, BF, tid);
    cp_commit();

    const int a_row = (lane & 15);
    const uint32_t a_cb = (uint32_t)((lane >> 4) << 4);
    const int b_row = (lane & 7) + ((lane & 16) >> 1);
    const uint32_t b_cb = (uint32_t)(((lane >> 3) & 1) << 4);

    for (int kc = 0; kc < JNK; kc++) {
        __syncthreads();            // all warps done reading the stage refilled below
        if (kc + 2 < JNK) {
            jload(sb, (kc + 2) % 3, m0, n0, (kc + 2) * 64, AF, BF, tid);
            cp_commit();
            cp_wait<2>();
        } else {
            cp_wait<0>();
        }
        __syncthreads();            // stage kc data visible
        uint32_t base = sb + (kc % 3) * JSTAGE;
        #pragma unroll
        for (int kk = 0; kk < 4; kk++) {
            uint32_t aF[8], bF[16];
            #pragma unroll
            for (int mf = 0; mf < 2; mf++) {
                uint32_t off = SW128((uint32_t)((m_warp + mf * 16 + a_row) * 128) + kk * 32 + a_cb);
                ldmx4(&aF[mf * 4], base + JOFF_A + off);
            }
            #pragma unroll
            for (int nf2 = 0; nf2 < 4; nf2++) {
                uint32_t off = SW128((uint32_t)((n_warp + nf2 * 16 + b_row) * 128) + kk * 32 + b_cb);
                ldmx4(&bF[nf2 * 4], base + JOFF_B + off);
            }
            #pragma unroll
            for (int mf = 0; mf < 2; mf++)
                #pragma unroll
                for (int nf = 0; nf < 8; nf++)
                    mma16816h(acc[mf][nf], &aF[mf * 4], &bF[nf * 2]);
        }
    }

    // epilogue: m16n8 C map — rows l/4, l/4+8; cols 2*(l%4)
    #pragma unroll
    for (int nf = 0; nf < 8; nf++) {
        int col = n0 + n_warp + nf * 8 + 2 * (lane & 3);
        float b0 = __ldg(&bias[col]);
        float b1 = __ldg(&bias[col + 1]);
        #pragma unroll
        for (int mf = 0; mf < 2; mf++) {
            int row = m0 + m_warp + mf * 16 + (lane >> 2);
            float2 v0 = make_float2(acc[mf][nf][0] + b0, acc[mf][nf][1] + b1);
            float2 v1 = make_float2(acc[mf][nf][2] + b0, acc[mf][nf][3] + b1);
            *(float2*)(C + (size_t)row * ODIM + col) = v0;
            *(float2*)(C + (size_t)(row + 8) * ODIM + col) = v1;
        }
    }
}

// ---------------- launcher ----------------
extern "C" void kernel_launch(void* const* d_in, const int* in_sizes, int n_in,
                              void* d_out, int out_size) {
    const float* hs_pad = (const float*)d_in[0];
    const int*   ys     = (const int*)  d_in[1];
    const float* embW   = (const float*)d_in[2];
    const float* W_ih0  = (const float*)d_in[3];
    const float* W_hh0  = (const float*)d_in[4];
    const float* b_ih0  = (const float*)d_in[5];
    const float* b_hh0  = (const float*)d_in[6];
    const float* W_ih1  = (const float*)d_in[7];
    const float* W_hh1  = (const float*)d_in[8];
    const float* b_ih1  = (const float*)d_in[9];
    const float* b_hh1  = (const float*)d_in[10];
    const float* W_enc  = (const float*)d_in[11];
    const float* b_enc  = (const float*)d_in[12];
    const float* W_dec  = (const float*)d_in[13];
    const float* b_dec  = (const float*)d_in[14];
    const float* W_out  = (const float*)d_in[15];
    const float* b_out  = (const float*)d_in[16];
    float* out = (float*)d_out;

    float *p_eys, *p_X0, *p_hdec, *p_enc, *p_dec;
    float *p_Wih0T, *p_WencT, *p_WdecT;
    __half *p_jntF, *p_WoutF;
    cudaGetSymbolAddress((void**)&p_eys, g_eys);
    cudaGetSymbolAddress((void**)&p_X0, g_X0);
    cudaGetSymbolAddress((void**)&p_hdec, g_hdec);
    cudaGetSymbolAddress((void**)&p_enc, g_enc);
    cudaGetSymbolAddress((void**)&p_dec, g_dec);
    cudaGetSymbolAddress((void**)&p_Wih0T, g_Wih0T);
    cudaGetSymbolAddress((void**)&p_WencT, g_WencT);
    cudaGetSymbolAddress((void**)&p_WdecT, g_WdecT);
    cudaGetSymbolAddress((void**)&p_jntF, g_jntF);
    cudaGetSymbolAddress((void**)&p_WoutF, g_WoutF);

    cudaFuncSetAttribute(joint_gemm_mma, cudaFuncAttributeMaxDynamicSharedMemorySize, JSM_TOTAL);

    dim3 tb(32, 8);
    transpose_kernel<<<dim3(EMBED / 32, 4 * DUNITS / 32), tb>>>(W_ih0, p_Wih0T, 4 * DUNITS, EMBED);
    transpose_kernel<<<dim3(EPROJS / 32, JOINT_ / 32), tb>>>(W_enc, p_WencT, JOINT_, EPROJS);
    transpose_kernel<<<dim3(DUNITS / 32, JOINT_ / 32), tb>>>(W_dec, p_WdecT, JOINT_, DUNITS);
    conv_wout_kernel<<<(ODIM * JOINT_ / 2 + 255) / 256, 256>>>(W_out);

    embed_kernel<<<U_ * B_, 128>>>(ys, embW);
    init_state_kernel<<<64, 256>>>();

    // X0 = eys @ W_ih0^T + b_ih0 + b_hh0
    gemm_f32x2<<<dim3(4 * DUNITS / 128, (U_ * B_ + 127) / 128), 256>>>(
        p_eys, p_Wih0T, b_ih0, b_hh0, p_X0, U_ * B_, 4 * DUNITS, EMBED);

    // whole 40-step 2-layer LSTM in one persistent kernel
    lstm_persistent<<<NBLK, 256>>>(W_hh0, W_ih1, W_hh1, b_ih1, b_hh1);

    // fused enc_proj + dec_proj (one wave: 65 blocks)
    gemm_encdec<<<dim3(JOINT_ / 128, 13), 256>>>(
        hs_pad, p_WencT, b_enc, p_enc, p_hdec, p_WdecT, b_dec, p_dec);

    tanh_split_kernel<<<(MROWS * (JOINT_ / 8) + 255) / 256, 256>>>();

    joint_gemm_mma<<<dim3(ODIM / 128, MROWS / 128), 256, JSM_TOTAL>>>(
        p_jntF, p_WoutF, b_out, out);
}

// round 14
// speedup vs baseline: 2.0941x; 1.0164x over previous
#include <cuda_runtime.h>
#include <cuda_bf16.h>
#include <cuda_fp16.h>
#include <math.h>
#include <stdint.h>

// Problem dims
#define B_      8
#define T_      150
#define U_      40
#define EPROJS  512
#define DUNITS  1024
#define EMBED   512
#define JOINT_  640
#define ODIM    1024

#define MROWS   (B_*T_*U_)     // 48000
#define NBLK    128            // persistent LSTM grid
#define NCHUNK_M 3             // tanh/joint pipeline chunks (125 m-tiles each)
#define MTILES_PER_CHUNK 125
#define ROWS_PER_CHUNK (MTILES_PER_CHUNK*128)   // 16000

// ---------------- device scratch (no allocation allowed) ----------------
__device__ float g_eys  [U_*B_*EMBED];
__device__ float g_X0   [U_*B_*4*DUNITS];
__device__ float g_h0   [2*B_*DUNITS];
__device__ float g_h1   [2*B_*DUNITS];
__device__ float g_c0   [B_*DUNITS];
__device__ float g_c1   [B_*DUNITS];
__device__ float g_hdec [B_*U_*DUNITS];
__device__ float g_enc  [B_*T_*JOINT_];
__device__ float g_dec  [B_*U_*JOINT_];
__device__ float g_Wih0T[EMBED*4*DUNITS];
__device__ float g_WencT[EPROJS*JOINT_];
__device__ float g_WdecT[DUNITS*JOINT_];
// fp16 operands for the tensor-core joint GEMM
__device__ __align__(16) __half g_jntF [MROWS*JOINT_];
__device__ __align__(16) __half g_WoutF[ODIM*JOINT_];
// grid barrier state
__device__ unsigned g_bar_count;
__device__ unsigned g_bar_sense;

// ---------------- f32x2 helpers ----------------
__device__ __forceinline__ unsigned long long pk2(float lo, float hi) {
    unsigned long long r;
    asm("mov.b64 %0, {%1, %2};" : "=l"(r) : "f"(lo), "f"(hi));
    return r;
}
__device__ __forceinline__ unsigned long long fma2(unsigned long long a,
                                                   unsigned long long b,
                                                   unsigned long long c) {
    unsigned long long d;
    asm("fma.rn.f32x2 %0, %1, %2, %3;" : "=l"(d) : "l"(a), "l"(b), "l"(c));
    return d;
}
__device__ __forceinline__ float2 upk2(unsigned long long v) {
    float2 r;
    asm("mov.b64 {%0, %1}, %2;" : "=f"(r.x), "=f"(r.y) : "l"(v));
    return r;
}
__device__ __forceinline__ float sigmf(float x) { return 1.0f / (1.0f + __expf(-x)); }

// ---------------- misc helpers ----------------
__device__ __forceinline__ uint32_t smem_u32(const void* p) {
    uint32_t a;
    asm("{ .reg .u64 t; cvta.to.shared.u64 t, %1; cvt.u32.u64 %0, t; }" : "=r"(a) : "l"(p));
    return a;
}
#define SW128(off) ((off) ^ (((off) >> 3) & 0x70))

__device__ __forceinline__ void cp_async16(uint32_t dst, const void* src) {
    asm volatile("cp.async.cg.shared.global [%0], [%1], 16;" :: "r"(dst), "l"(src));
}
__device__ __forceinline__ void cp_commit() { asm volatile("cp.async.commit_group;" ::: "memory"); }
template<int N> __device__ __forceinline__ void cp_wait() {
    asm volatile("cp.async.wait_group %0;" :: "n"(N) : "memory");
}
__device__ __forceinline__ void ldmx4(uint32_t* r, uint32_t addr) {
    asm volatile("ldmatrix.sync.aligned.m8n8.x4.shared.b16 {%0,%1,%2,%3}, [%4];"
                 : "=r"(r[0]), "=r"(r[1]), "=r"(r[2]), "=r"(r[3]) : "r"(addr));
}
__device__ __forceinline__ void mma16816h(float* c, const uint32_t* a, const uint32_t* b) {
    asm volatile(
        "mma.sync.aligned.m16n8k16.row.col.f32.f16.f16.f32 "
        "{%0,%1,%2,%3}, {%4,%5,%6,%7}, {%8,%9}, {%0,%1,%2,%3};"
        : "+f"(c[0]), "+f"(c[1]), "+f"(c[2]), "+f"(c[3])
        : "r"(a[0]), "r"(a[1]), "r"(a[2]), "r"(a[3]), "r"(b[0]), "r"(b[1]));
}
__device__ __forceinline__ unsigned ld_acq(unsigned* p) {
    unsigned v;
    asm volatile("ld.acquire.gpu.u32 %0, [%1];" : "=r"(v) : "l"(p) : "memory");
    return v;
}
__device__ __forceinline__ unsigned atom_add_acqrel(unsigned* p, unsigned v) {
    unsigned old;
    asm volatile("atom.acq_rel.gpu.add.u32 %0, [%1], %2;" : "=r"(old) : "l"(p), "r"(v) : "memory");
    return old;
}
__device__ __forceinline__ void red_add_release(unsigned* p, unsigned v) {
    asm volatile("red.release.gpu.add.u32 [%0], %1;" :: "l"(p), "r"(v) : "memory");
}

// ---------------- transpose ----------------
__global__ void transpose_kernel(const float* __restrict__ W, float* __restrict__ Wt,
                                 int N, int K) {
    __shared__ float t[32][33];
    int kb = blockIdx.x * 32, nb = blockIdx.y * 32;
    int x = threadIdx.x, y = threadIdx.y;
    #pragma unroll
    for (int yy = y; yy < 32; yy += 8) {
        int n = nb + yy, k = kb + x;
        if (n < N && k < K) t[yy][x] = W[(size_t)n * K + k];
    }
    __syncthreads();
    #pragma unroll
    for (int yy = y; yy < 32; yy += 8) {
        int k = kb + yy, n = nb + x;
        if (k < K && n < N) Wt[(size_t)k * N + n] = t[x][yy];
    }
}

// ---------------- embedding gather ----------------
__global__ void embed_kernel(const int* __restrict__ ys, const float* __restrict__ embW) {
    int row = blockIdx.x;            // u*8 + b
    int u = row >> 3, b = row & 7;
    int tok = ys[b * U_ + u];
    const float4* src = (const float4*)(embW + (size_t)tok * EMBED);
    float4* dst = (float4*)(g_eys + (size_t)row * EMBED);
    for (int i = threadIdx.x; i < EMBED / 4; i += blockDim.x) dst[i] = src[i];
}

__global__ void init_state_kernel() {
    int i = blockIdx.x * blockDim.x + threadIdx.x;
    if (i == 0) g_bar_count = 0;
    if (i < 2 * B_ * DUNITS) { g_h0[i] = 0.f; g_h1[i] = 0.f; }
    if (i < B_ * DUNITS)     { g_c0[i] = 0.f; g_c1[i] = 0.f; }
}

// ---------------- convert W_out to fp16 ----------------
__global__ void conv_wout_kernel(const float* __restrict__ W) {
    int i = blockIdx.x * blockDim.x + threadIdx.x;
    if (i < ODIM * JOINT_ / 2) {
        float2 w = ((const float2*)W)[i];
        ((__half2*)g_WoutF)[i] = __floats2half2_rn(w.x, w.y);
    }
}

// ---------------- fp32 GEMM via FFMA2 (small GEMMs) ----------------
__global__ __launch_bounds__(256, 2)
void gemm_f32x2(const float* __restrict__ A, const float* __restrict__ Wt,
                const float* __restrict__ bias1, const float* __restrict__ bias2,
                float* __restrict__ C, int M, int N, int K) {
    __shared__ float As[128][16];
    __shared__ float Bs[16][128];
    const int tid = threadIdx.x;
    const int m0 = blockIdx.y * 128;
    const int n0 = blockIdx.x * 128;
    const int tr = tid >> 4;
    const int tc = tid & 15;
    const int lr = tid >> 2;
    const int lk = (tid & 3) << 2;
    const int kr = tid >> 5;
    const int kc = (tid & 31) << 2;

    unsigned long long acc[8][4];
    #pragma unroll
    for (int i = 0; i < 8; i++)
        #pragma unroll
        for (int p = 0; p < 4; p++) acc[i][p] = 0ull;

    for (int kt = 0; kt < K; kt += 16) {
        #pragma unroll
        for (int h = 0; h < 2; h++) {
            int m = lr + h * 64;
            int gm = m0 + m;
            float4 v = make_float4(0.f, 0.f, 0.f, 0.f);
            if (gm < M) v = *(const float4*)(A + (size_t)gm * K + kt + lk);
            *(float4*)(&As[m][lk]) = v;
            int k = kr + h * 8;
            float4 w = *(const float4*)(Wt + (size_t)(kt + k) * N + n0 + kc);
            *(float4*)(&Bs[k][kc]) = w;
        }
        __syncthreads();
        const float* ap = &As[tr * 8][0];
        const float4* bp = (const float4*)&Bs[0][tc * 8];
        #pragma unroll
        for (int k = 0; k < 16; k++) {
            float4 bv0 = bp[k * 32];
            float4 bv1 = bp[k * 32 + 1];
            unsigned long long bpk[4];
            bpk[0] = pk2(bv0.x, bv0.y);
            bpk[1] = pk2(bv0.z, bv0.w);
            bpk[2] = pk2(bv1.x, bv1.y);
            bpk[3] = pk2(bv1.z, bv1.w);
            #pragma unroll
            for (int i = 0; i < 8; i++) {
                float a = ap[i * 16 + k];
                unsigned long long a2 = pk2(a, a);
                #pragma unroll
                for (int p = 0; p < 4; p++) acc[i][p] = fma2(a2, bpk[p], acc[i][p]);
            }
        }
        __syncthreads();
    }
    float bias[8];
    #pragma unroll
    for (int i = 0; i < 8; i++) {
        int n = n0 + tc * 8 + i;
        float bb = bias1[n];
        if (bias2) bb += bias2[n];
        bias[i] = bb;
    }
    #pragma unroll
    for (int i = 0; i < 8; i++) {
        int gm = m0 + tr * 8 + i;
        if (gm < M) {
            float2 v0 = upk2(acc[i][0]);
            float2 v1 = upk2(acc[i][1]);
            float2 v2 = upk2(acc[i][2]);
            float2 v3 = upk2(acc[i][3]);
            float4 o0 = make_float4(v0.x + bias[0], v0.y + bias[1], v1.x + bias[2], v1.y + bias[3]);
            float4 o1 = make_float4(v2.x + bias[4], v2.y + bias[5], v3.x + bias[6], v3.y + bias[7]);
            float* cp = C + (size_t)gm * N + n0 + tc * 8;
            *(float4*)cp = o0;
            *(float4*)(cp + 4) = o1;
        }
    }
}

// ---------------- persistent LSTM (f32x2 accum, software grid barrier) ----------------
__device__ __forceinline__ void lstm_load_h(float* hs, const float* __restrict__ src, int tid) {
    const float4* s = (const float4*)src;
    float4* d = (float4*)hs;
    #pragma unroll
    for (int i = 0; i < 8; i++) d[tid + 256 * i] = s[tid + 256 * i];
}

// packed f32x2 accumulate: acc2[r][b] holds (even,odd) partial sums
__device__ __forceinline__ void lstm_accum2(unsigned long long acc2[4][8],
                                            const float* __restrict__ W,
                                            const float4* hs4, int j, int lane) {
    const float4* W4 = (const float4*)W;
    #pragma unroll 2
    for (int k0 = 0; k0 < 256; k0 += 32) {
        unsigned long long w01[4], w23[4];
        #pragma unroll
        for (int r = 0; r < 4; r++) {
            float4 w = __ldg(&W4[(size_t)(r * DUNITS + j) * 256 + k0 + lane]);
            w01[r] = pk2(w.x, w.y);
            w23[r] = pk2(w.z, w.w);
        }
        #pragma unroll
        for (int b = 0; b < 8; b++) {
            float4 hv = hs4[b * 256 + k0 + lane];
            unsigned long long h01 = pk2(hv.x, hv.y);
            unsigned long long h23 = pk2(hv.z, hv.w);
            #pragma unroll
            for (int r = 0; r < 4; r++) {
                acc2[r][b] = fma2(w01[r], h01, acc2[r][b]);
                acc2[r][b] = fma2(w23[r], h23, acc2[r][b]);
            }
        }
    }
}

__device__ __forceinline__ void lstm_finalize(float acc[4][8], unsigned long long acc2[4][8]) {
    #pragma unroll
    for (int r = 0; r < 4; r++)
        #pragma unroll
        for (int b = 0; b < 8; b++) {
            float2 v = upk2(acc2[r][b]);
            acc[r][b] = v.x + v.y;
        }
    #pragma unroll
    for (int r = 0; r < 4; r++)
        #pragma unroll
        for (int b = 0; b < 8; b++)
            #pragma unroll
            for (int off = 16; off; off >>= 1)
                acc[r][b] += __shfl_xor_sync(0xffffffffu, acc[r][b], off);
}

__device__ __forceinline__ void grid_sync_(unsigned& gen) {
    __threadfence();
    __syncthreads();
    if (threadIdx.x == 0) {
        if (atom_add_acqrel(&g_bar_count, 1) == NBLK - 1) {
            g_bar_count = 0;
            red_add_release(&g_bar_sense, 1);
        } else {
            while (ld_acq(&g_bar_sense) == gen) { __nanosleep(64); }
        }
    }
    __syncthreads();
    gen++;
}

__global__ __launch_bounds__(256, 1)
void lstm_persistent(const float* __restrict__ Whh0,
                     const float* __restrict__ Wih1, const float* __restrict__ Whh1,
                     const float* __restrict__ bih1, const float* __restrict__ bhh1) {
    __shared__ float hs[B_ * DUNITS];
    int tid = threadIdx.x, lane = tid & 31, warp = tid >> 5;
    int j = blockIdx.x * 8 + warp;
    unsigned gen = ld_acq(&g_bar_sense);   // stable at kernel start

    for (int u = 0; u < U_; u++) {
        int cur = u & 1, prev = cur ^ 1;
        const float* h0prev = g_h0 + prev * B_ * DUNITS;
        float* h0cur = g_h0 + cur * B_ * DUNITS;
        const float* h1prev = g_h1 + prev * B_ * DUNITS;
        float* h1cur = g_h1 + cur * B_ * DUNITS;

        // -------- cell 0 --------
        lstm_load_h(hs, h0prev, tid);
        __syncthreads();
        {
            unsigned long long acc2[4][8];
            #pragma unroll
            for (int r = 0; r < 4; r++)
                #pragma unroll
                for (int b = 0; b < 8; b++) acc2[r][b] = 0ull;
            lstm_accum2(acc2, Whh0, (const float4*)hs, j, lane);
            float acc[4][8];
            lstm_finalize(acc, acc2);
            if (lane < 8) {
                int b = lane;
                const float* x0 = &g_X0[(size_t)(u * 8 + b) * 4 * DUNITS];
                float gi = acc[0][b] + x0[j];
                float gf = acc[1][b] + x0[DUNITS + j];
                float gg = acc[2][b] + x0[2 * DUNITS + j];
                float go = acc[3][b] + x0[3 * DUNITS + j];
                float c = g_c0[b * DUNITS + j];
                float cn = sigmf(gf) * c + sigmf(gi) * tanhf(gg);
                float hn = sigmf(go) * tanhf(cn);
                g_c0[b * DUNITS + j] = cn;
                h0cur[b * DUNITS + j] = hn;
            }
        }
        grid_sync_(gen);

        // -------- cell 1 --------
        {
            unsigned long long acc2[4][8];
            #pragma unroll
            for (int r = 0; r < 4; r++)
                #pragma unroll
                for (int b = 0; b < 8; b++) acc2[r][b] = 0ull;
            lstm_load_h(hs, h0cur, tid);
            __syncthreads();
            lstm_accum2(acc2, Wih1, (const float4*)hs, j, lane);
            __syncthreads();
            lstm_load_h(hs, h1prev, tid);
            __syncthreads();
            lstm_accum2(acc2, Whh1, (const float4*)hs, j, lane);
            float acc[4][8];
            lstm_finalize(acc, acc2);
            if (lane < 8) {
                int b = lane;
                float gi = acc[0][b] + bih1[j] + bhh1[j];
                float gf = acc[1][b] + bih1[DUNITS + j] + bhh1[DUNITS + j];
                float gg = acc[2][b] + bih1[2 * DUNITS + j] + bhh1[2 * DUNITS + j];
                float go = acc[3][b] + bih1[3 * DUNITS + j] + bhh1[3 * DUNITS + j];
                float c = g_c1[b * DUNITS + j];
                float cn = sigmf(gf) * c + sigmf(gi) * tanhf(gg);
                float hn = sigmf(go) * tanhf(cn);
                g_c1[b * DUNITS + j] = cn;
                h1cur[b * DUNITS + j] = hn;
                g_hdec[(size_t)(b * U_ + u) * DUNITS + j] = hn;
            }
        }
        if (u + 1 < U_) grid_sync_(gen);
    }
}

// ---------------- joint tanh -> fp16 (chunked) ----------------
__global__ void tanh_split_kernel(int row_base) {
    int idx = blockIdx.x * blockDim.x + threadIdx.x;     // per 8 elements
    const int TOT8 = ROWS_PER_CHUNK * (JOINT_ / 8);
    if (idx >= TOT8) return;
    int row = row_base + idx / (JOINT_ / 8);
    int j8 = idx % (JOINT_ / 8);
    int u = row % U_;
    int bt = row / U_;
    int b = bt / T_;
    const float4* e4 = (const float4*)&g_enc[(size_t)bt * JOINT_ + j8 * 8];
    const float4* d4 = (const float4*)&g_dec[(size_t)(b * U_ + u) * JOINT_ + j8 * 8];
    __half2 hp[4];
    #pragma unroll
    for (int q = 0; q < 2; q++) {
        float4 e = e4[q], d = d4[q];
        hp[q * 2 + 0] = __floats2half2_rn(tanhf(e.x + d.x), tanhf(e.y + d.y));
        hp[q * 2 + 1] = __floats2half2_rn(tanhf(e.z + d.z), tanhf(e.w + d.w));
    }
    *(uint4*)&g_jntF[(size_t)row * JOINT_ + j8 * 8] = *(uint4*)hp;
}

// ---------------- joint GEMM: single-pass fp16 mma.sync, 3-stage cp.async ----------------
#define JSTAGE   32768
#define JOFF_A   0
#define JOFF_B   16384
#define JSM_TOTAL (3 * JSTAGE)   // 98304 -> 2 CTAs/SM
#define JNK      10              // 640 / 64

__device__ __forceinline__ void jload(uint32_t sb, int stage, int m0, int n0, int kt,
                                      const __half* __restrict__ AF,
                                      const __half* __restrict__ BF, int tid) {
    uint32_t base = sb + stage * JSTAGE;
    #pragma unroll
    for (int ii = 0; ii < 8; ii++) {
        const int mat = ii >> 2;                 // 0=A 1=B
        int idx = (ii & 3) * 256 + tid;
        int r = idx >> 3, c = idx & 7;
        const __half* g = (mat == 0) ? AF : BF;
        int grow = (mat == 0 ? m0 : n0) + r;
        const char* src = (const char*)(g + (size_t)grow * JOINT_ + kt) + c * 16;
        uint32_t dst = base + mat * 16384 + SW128((uint32_t)(r * 128 + c * 16));
        cp_async16(dst, src);
    }
}

__global__ void __launch_bounds__(256, 2)
joint_gemm_mma(const __half* __restrict__ AF, const __half* __restrict__ BF,
               const float* __restrict__ bias, float* __restrict__ C, int mtile_base) {
    extern __shared__ char smem[];
    uint32_t sb = smem_u32(smem);
    const int tid = threadIdx.x, lane = tid & 31, wid = tid >> 5;
    const int m0 = (mtile_base + blockIdx.y) * 128, n0 = blockIdx.x * 128;
    const int m_warp = (wid >> 1) * 32;        // 0,32,64,96
    const int n_warp = (wid & 1) * 64;         // 0,64

    float acc[2][8][4];
    #pragma unroll
    for (int mf = 0; mf < 2; mf++)
        #pragma unroll
        for (int nf = 0; nf < 8; nf++)
            #pragma unroll
            for (int q = 0; q < 4; q++) acc[mf][nf][q] = 0.f;

    jload(sb, 0, m0, n0, 0, AF, BF, tid);
    cp_commit();
    jload(sb, 1, m0, n0, 64, AF, BF, tid);
    cp_commit();

    const int a_row = (lane & 15);
    const uint32_t a_cb = (uint32_t)((lane >> 4) << 4);
    const int b_row = (lane & 7) + ((lane & 16) >> 1);
    const uint32_t b_cb = (uint32_t)(((lane >> 3) & 1) << 4);

    for (int kc = 0; kc < JNK; kc++) {
        __syncthreads();
        if (kc + 2 < JNK) {
            jload(sb, (kc + 2) % 3, m0, n0, (kc + 2) * 64, AF, BF, tid);
            cp_commit();
            cp_wait<2>();
        } else {
            cp_wait<0>();
        }
        __syncthreads();
        uint32_t base = sb + (kc % 3) * JSTAGE;
        #pragma unroll
        for (int kk = 0; kk < 4; kk++) {
            uint32_t aF[8], bF[16];
            #pragma unroll
            for (int mf = 0; mf < 2; mf++) {
                uint32_t off = SW128((uint32_t)((m_warp + mf * 16 + a_row) * 128) + kk * 32 + a_cb);
                ldmx4(&aF[mf * 4], base + JOFF_A + off);
            }
            #pragma unroll
            for (int nf2 = 0; nf2 < 4; nf2++) {
                uint32_t off = SW128((uint32_t)((n_warp + nf2 * 16 + b_row) * 128) + kk * 32 + b_cb);
                ldmx4(&bF[nf2 * 4], base + JOFF_B + off);
            }
            #pragma unroll
            for (int mf = 0; mf < 2; mf++)
                #pragma unroll
                for (int nf = 0; nf < 8; nf++)
                    mma16816h(acc[mf][nf], &aF[mf * 4], &bF[nf * 2]);
        }
    }

    #pragma unroll
    for (int nf = 0; nf < 8; nf++) {
        int col = n0 + n_warp + nf * 8 + 2 * (lane & 3);
        float b0 = __ldg(&bias[col]);
        float b1 = __ldg(&bias[col + 1]);
        #pragma unroll
        for (int mf = 0; mf < 2; mf++) {
            int row = m0 + m_warp + mf * 16 + (lane >> 2);
            float2 v0 = make_float2(acc[mf][nf][0] + b0, acc[mf][nf][1] + b1);
            float2 v1 = make_float2(acc[mf][nf][2] + b0, acc[mf][nf][3] + b1);
            *(float2*)(C + (size_t)row * ODIM + col) = v0;
            *(float2*)(C + (size_t)(row + 8) * ODIM + col) = v1;
        }
    }
}

// ---------------- launcher (multi-stream captured pipeline) ----------------
// Streams/events are created ONCE on the first (eager, pre-capture) call and
// cached. The capture call replays only launch/record/wait ops — the standard
// cross-stream capture idiom. If stream creation fails we fall back to the
// default stream (serial, still correct).
extern "C" void kernel_launch(void* const* d_in, const int* in_sizes, int n_in,
                              void* d_out, int out_size) {
    const float* hs_pad = (const float*)d_in[0];
    const int*   ys     = (const int*)  d_in[1];
    const float* embW   = (const float*)d_in[2];
    const float* W_ih0  = (const float*)d_in[3];
    const float* W_hh0  = (const float*)d_in[4];
    const float* b_ih0  = (const float*)d_in[5];
    const float* b_hh0  = (const float*)d_in[6];
    const float* W_ih1  = (const float*)d_in[7];
    const float* W_hh1  = (const float*)d_in[8];
    const float* b_ih1  = (const float*)d_in[9];
    const float* b_hh1  = (const float*)d_in[10];
    const float* W_enc  = (const float*)d_in[11];
    const float* b_enc  = (const float*)d_in[12];
    const float* W_dec  = (const float*)d_in[13];
    const float* b_dec  = (const float*)d_in[14];
    const float* W_out  = (const float*)d_in[15];
    const float* b_out  = (const float*)d_in[16];
    float* out = (float*)d_out;

    float *p_eys, *p_X0, *p_hdec, *p_enc, *p_dec;
    float *p_Wih0T, *p_WencT, *p_WdecT;
    __half *p_jntF, *p_WoutF;
    cudaGetSymbolAddress((void**)&p_eys, g_eys);
    cudaGetSymbolAddress((void**)&p_X0, g_X0);
    cudaGetSymbolAddress((void**)&p_hdec, g_hdec);
    cudaGetSymbolAddress((void**)&p_enc, g_enc);
    cudaGetSymbolAddress((void**)&p_dec, g_dec);
    cudaGetSymbolAddress((void**)&p_Wih0T, g_Wih0T);
    cudaGetSymbolAddress((void**)&p_WencT, g_WencT);
    cudaGetSymbolAddress((void**)&p_WdecT, g_WdecT);
    cudaGetSymbolAddress((void**)&p_jntF, g_jntF);
    cudaGetSymbolAddress((void**)&p_WoutF, g_WoutF);

    // one-time resources (created outside graph capture on the eager call)
    static bool s_init = false;
    static cudaStream_t s2 = 0, sB = 0;
    static cudaEvent_t evRoot = 0, evEnc = 0, evJ = 0;
    static cudaEvent_t evT[NCHUNK_M] = {};
    if (!s_init) {
        cudaFuncSetAttribute(joint_gemm_mma, cudaFuncAttributeMaxDynamicSharedMemorySize, JSM_TOTAL);
        if (cudaStreamCreateWithFlags(&s2, cudaStreamNonBlocking) != cudaSuccess) s2 = 0;
        if (cudaStreamCreateWithFlags(&sB, cudaStreamNonBlocking) != cudaSuccess) sB = 0;
        cudaEventCreateWithFlags(&evRoot, cudaEventDisableTiming);
        cudaEventCreateWithFlags(&evEnc, cudaEventDisableTiming);
        for (int c = 0; c < NCHUNK_M; c++) cudaEventCreateWithFlags(&evT[c], cudaEventDisableTiming);
        cudaEventCreateWithFlags(&evJ, cudaEventDisableTiming);
        s_init = true;
    }

    dim3 tb(32, 8);

    // fork side stream s2 (input-only work: enc path + W_out conversion)
    cudaEventRecord(evRoot, 0);
    cudaStreamWaitEvent(s2, evRoot, 0);
    transpose_kernel<<<dim3(EPROJS / 32, JOINT_ / 32), tb, 0, s2>>>(W_enc, p_WencT, JOINT_, EPROJS);
    conv_wout_kernel<<<(ODIM * JOINT_ / 2 + 255) / 256, 256, 0, s2>>>(W_out);
    gemm_f32x2<<<dim3(JOINT_ / 128, (B_ * T_ + 127) / 128), 256, 0, s2>>>(
        hs_pad, p_WencT, b_enc, nullptr, p_enc, B_ * T_, JOINT_, EPROJS);
    cudaEventRecord(evEnc, s2);

    // main stream: decoder path
    transpose_kernel<<<dim3(EMBED / 32, 4 * DUNITS / 32), tb>>>(W_ih0, p_Wih0T, 4 * DUNITS, EMBED);
    transpose_kernel<<<dim3(DUNITS / 32, JOINT_ / 32), tb>>>(W_dec, p_WdecT, JOINT_, DUNITS);
    embed_kernel<<<U_ * B_, 128>>>(ys, embW);
    init_state_kernel<<<64, 256>>>();

    gemm_f32x2<<<dim3(4 * DUNITS / 128, (U_ * B_ + 127) / 128), 256>>>(
        p_eys, p_Wih0T, b_ih0, b_hh0, p_X0, U_ * B_, 4 * DUNITS, EMBED);

    lstm_persistent<<<NBLK, 256>>>(W_hh0, W_ih1, W_hh1, b_ih1, b_hh1);

    gemm_f32x2<<<dim3(JOINT_ / 128, (B_ * U_ + 127) / 128), 256>>>(
        p_hdec, p_WdecT, b_dec, nullptr, p_dec, B_ * U_, JOINT_, DUNITS);

    // join enc before tanh
    cudaStreamWaitEvent(0, evEnc, 0);

    // tanh (main) / joint GEMM (sB) software pipeline over 3 m-chunks
    const int TGRID = (ROWS_PER_CHUNK * (JOINT_ / 8) + 255) / 256;
    for (int c = 0; c < NCHUNK_M; c++) {
        tanh_split_kernel<<<TGRID, 256>>>(c * ROWS_PER_CHUNK);
        cudaEventRecord(evT[c], 0);
        cudaStreamWaitEvent(sB, evT[c], 0);
        joint_gemm_mma<<<dim3(ODIM / 128, MTILES_PER_CHUNK), 256, JSM_TOTAL, sB>>>(
            p_jntF, p_WoutF, b_out, out, c * MTILES_PER_CHUNK);
    }
    cudaEventRecord(evJ, sB);
    cudaStreamWaitEvent(0, evJ, 0);
}